// round 2
// baseline (speedup 1.0000x reference)
#include <cuda_runtime.h>
#include <math.h>

// Problem constants
#define B_SZ    2
#define S_LEN   2048
#define D_MODEL 1024
#define NHEAD   16
#define DKH     64          // head dim
#define MROWS   (B_SZ * S_LEN)   // 4096

// Scratch (device globals; allocation inside kernel_launch is forbidden)
__device__ float g_Q [B_SZ * S_LEN * D_MODEL];
__device__ float g_K [B_SZ * S_LEN * D_MODEL];
__device__ float g_V [B_SZ * S_LEN * D_MODEL];
__device__ float g_AO[B_SZ * S_LEN * D_MODEL];

// ---------------------------------------------------------------------------
// SGEMM NT: C[m][n] = sum_k A[m*K+k] * B[n*K+k]
// BM=BN=128, BK=16, 256 threads, 8x8 micro-tile per thread.
// A: [M,K] row-major, B: [N,K] row-major (nn.Linear weight [out,in]).
// M,N divisible by 128, K divisible by 16 (always true here).
// ---------------------------------------------------------------------------
__global__ __launch_bounds__(256)
void sgemm_nt(const float* __restrict__ A, const float* __restrict__ Bm,
              float* __restrict__ C, int M, int N, int K)
{
    __shared__ float As[16][128];   // transposed: As[k][m]
    __shared__ float Bs[16][128];   // transposed: Bs[k][n]

    const int tid = threadIdx.x;
    const int tx  = tid & 15;        // 0..15 -> n
    const int ty  = tid >> 4;        // 0..15 -> m
    const int row0 = blockIdx.y * 128;
    const int col0 = blockIdx.x * 128;

    float acc[8][8];
    #pragma unroll
    for (int i = 0; i < 8; i++)
        #pragma unroll
        for (int j = 0; j < 8; j++) acc[i][j] = 0.f;

    for (int k0 = 0; k0 < K; k0 += 16) {
        // Load 128x16 tiles of A and B, store transposed.
        #pragma unroll
        for (int it = 0; it < 2; it++) {
            int idx = tid + it * 256;      // 0..511
            int r   = idx >> 2;            // 0..127
            int c4  = (idx & 3) << 2;      // 0,4,8,12
            float4 va = *(const float4*)&A [(size_t)(row0 + r) * K + k0 + c4];
            As[c4+0][r] = va.x; As[c4+1][r] = va.y;
            As[c4+2][r] = va.z; As[c4+3][r] = va.w;
            float4 vb = *(const float4*)&Bm[(size_t)(col0 + r) * K + k0 + c4];
            Bs[c4+0][r] = vb.x; Bs[c4+1][r] = vb.y;
            Bs[c4+2][r] = vb.z; Bs[c4+3][r] = vb.w;
        }
        __syncthreads();

        #pragma unroll
        for (int k = 0; k < 16; k++) {
            float a[8], b[8];
            *(float4*)&a[0] = *(float4*)&As[k][ty * 8];
            *(float4*)&a[4] = *(float4*)&As[k][ty * 8 + 4];
            *(float4*)&b[0] = *(float4*)&Bs[k][tx * 8];
            *(float4*)&b[4] = *(float4*)&Bs[k][tx * 8 + 4];
            #pragma unroll
            for (int i = 0; i < 8; i++)
                #pragma unroll
                for (int j = 0; j < 8; j++)
                    acc[i][j] = fmaf(a[i], b[j], acc[i][j]);
        }
        __syncthreads();
    }

    // Writeback
    #pragma unroll
    for (int i = 0; i < 8; i++) {
        size_t base = (size_t)(row0 + ty * 8 + i) * N + col0 + tx * 8;
        float4 v0 = make_float4(acc[i][0], acc[i][1], acc[i][2], acc[i][3]);
        float4 v1 = make_float4(acc[i][4], acc[i][5], acc[i][6], acc[i][7]);
        *(float4*)&C[base]     = v0;
        *(float4*)&C[base + 4] = v1;
    }
}

// ---------------------------------------------------------------------------
// Fused causal flash attention, fp32.
// Grid: (S/64, H, B). Block: 256 threads (16x16; 4x4 micro-tile).
// Q tile 64x64 (pre-scaled by 1/8), K/V tiles 64x64.
// smem: Qs_t[d][m] | KP (Ks_t[d][n], later Ps_t[n][m]) | Vs[n][d]  = 48KB dyn.
// Online softmax state (running max / sum) replicated across the 16 lanes
// that share a row group; reductions via shfl_xor width-16.
// ---------------------------------------------------------------------------
__global__ __launch_bounds__(256)
void attn_causal(const float* __restrict__ Q, const float* __restrict__ K,
                 const float* __restrict__ V, float* __restrict__ O)
{
    extern __shared__ float smem[];
    float* Qs = smem;              // [64][64]  Qs[d*64+m]
    float* KP = smem + 64 * 64;    // [64][64]  Ks[d*64+n]  /  Ps[n*64+m]
    float* Vs = smem + 2 * 64 * 64;// [64][64]  Vs[n*64+d]

    const int tid = threadIdx.x;
    const int tx  = tid & 15;      // -> key col group / dk col group
    const int ty  = tid >> 4;      // -> query row group
    const int qt  = blockIdx.x;    // q tile
    const int h   = blockIdx.y;
    const int b   = blockIdx.z;
    const int q0  = qt * 64;

    const size_t headoff = (size_t)h * DKH;

    // Load Q tile transposed, pre-scaled by 1/sqrt(dk)=0.125
    #pragma unroll
    for (int it = 0; it < 4; it++) {
        int idx = tid + it * 256;          // 0..1023
        int m   = idx >> 4;                // 0..63
        int d4  = (idx & 15) << 2;         // 0..60
        float4 v = *(const float4*)&Q[((size_t)(b * S_LEN + q0 + m)) * D_MODEL + headoff + d4];
        Qs[(d4+0)*64 + m] = v.x * 0.125f;
        Qs[(d4+1)*64 + m] = v.y * 0.125f;
        Qs[(d4+2)*64 + m] = v.z * 0.125f;
        Qs[(d4+3)*64 + m] = v.w * 0.125f;
    }

    float o[4][4];
    #pragma unroll
    for (int i = 0; i < 4; i++)
        #pragma unroll
        for (int j = 0; j < 4; j++) o[i][j] = 0.f;
    float mi[4] = {-1e30f, -1e30f, -1e30f, -1e30f};
    float li[4] = {0.f, 0.f, 0.f, 0.f};

    for (int jt = 0; jt <= qt; jt++) {
        __syncthreads();   // protect KP/Vs from previous iteration readers
        const int k0 = jt * 64;
        // Load K tile transposed into KP, V tile natural into Vs
        #pragma unroll
        for (int it = 0; it < 4; it++) {
            int idx = tid + it * 256;
            int n   = idx >> 4;
            int d4  = (idx & 15) << 2;
            float4 vk = *(const float4*)&K[((size_t)(b * S_LEN + k0 + n)) * D_MODEL + headoff + d4];
            KP[(d4+0)*64 + n] = vk.x;
            KP[(d4+1)*64 + n] = vk.y;
            KP[(d4+2)*64 + n] = vk.z;
            KP[(d4+3)*64 + n] = vk.w;
            float4 vv = *(const float4*)&V[((size_t)(b * S_LEN + k0 + n)) * D_MODEL + headoff + d4];
            *(float4*)&Vs[n * 64 + d4] = vv;
        }
        __syncthreads();

        // scores s[i][j] = sum_d Qs[d][ty*4+i] * Ks[d][tx*4+j]   (pre-scaled)
        float s[4][4];
        #pragma unroll
        for (int i = 0; i < 4; i++)
            #pragma unroll
            for (int j = 0; j < 4; j++) s[i][j] = 0.f;
        #pragma unroll 8
        for (int d = 0; d < 64; d++) {
            float4 a4 = *(const float4*)&Qs[d * 64 + ty * 4];
            float4 b4 = *(const float4*)&KP[d * 64 + tx * 4];
            float a[4] = {a4.x, a4.y, a4.z, a4.w};
            float bb[4] = {b4.x, b4.y, b4.z, b4.w};
            #pragma unroll
            for (int i = 0; i < 4; i++)
                #pragma unroll
                for (int j = 0; j < 4; j++)
                    s[i][j] = fmaf(a[i], bb[j], s[i][j]);
        }

        // causal mask on diagonal tile (tile-aligned: compare within-tile idx)
        if (jt == qt) {
            #pragma unroll
            for (int i = 0; i < 4; i++)
                #pragma unroll
                for (int j = 0; j < 4; j++)
                    if (tx * 4 + j > ty * 4 + i) s[i][j] = -1e30f;
        }

        // online softmax, row stats replicated across the 16-lane row group
        #pragma unroll
        for (int i = 0; i < 4; i++) {
            float rmax = fmaxf(fmaxf(s[i][0], s[i][1]), fmaxf(s[i][2], s[i][3]));
            #pragma unroll
            for (int off = 8; off >= 1; off >>= 1)
                rmax = fmaxf(rmax, __shfl_xor_sync(0xffffffffu, rmax, off));
            float mnew  = fmaxf(mi[i], rmax);
            float alpha = __expf(mi[i] - mnew);
            float rsum  = 0.f;
            #pragma unroll
            for (int j = 0; j < 4; j++) {
                s[i][j] = __expf(s[i][j] - mnew);
                rsum += s[i][j];
            }
            #pragma unroll
            for (int off = 8; off >= 1; off >>= 1)
                rsum += __shfl_xor_sync(0xffffffffu, rsum, off);
            li[i] = li[i] * alpha + rsum;
            mi[i] = mnew;
            #pragma unroll
            for (int j = 0; j < 4; j++) o[i][j] *= alpha;
        }

        __syncthreads();   // all reads of Ks done -> reuse KP for P
        // write P transposed: Ps[n][m]
        #pragma unroll
        for (int j = 0; j < 4; j++) {
            float4 pv = make_float4(s[0][j], s[1][j], s[2][j], s[3][j]);
            *(float4*)&KP[(tx * 4 + j) * 64 + ty * 4] = pv;
        }
        __syncthreads();

        // O[i][j] += sum_n Ps[n][ty*4+i] * Vs[n][tx*4+j]
        #pragma unroll 8
        for (int n = 0; n < 64; n++) {
            float4 p4 = *(const float4*)&KP[n * 64 + ty * 4];
            float4 v4 = *(const float4*)&Vs[n * 64 + tx * 4];
            float p[4] = {p4.x, p4.y, p4.z, p4.w};
            float vv[4] = {v4.x, v4.y, v4.z, v4.w};
            #pragma unroll
            for (int i = 0; i < 4; i++)
                #pragma unroll
                for (int j = 0; j < 4; j++)
                    o[i][j] = fmaf(p[i], vv[j], o[i][j]);
        }
    }

    // epilogue: normalize and store to [B,S,D] with D index = h*64 + d
    #pragma unroll
    for (int i = 0; i < 4; i++) {
        float inv = 1.f / li[i];
        float4 v = make_float4(o[i][0] * inv, o[i][1] * inv,
                               o[i][2] * inv, o[i][3] * inv);
        size_t base = ((size_t)(b * S_LEN + q0 + ty * 4 + i)) * D_MODEL + headoff + tx * 4;
        *(float4*)&O[base] = v;
    }
}

// ---------------------------------------------------------------------------
// Launch
// ---------------------------------------------------------------------------
extern "C" void kernel_launch(void* const* d_in, const int* in_sizes, int n_in,
                              void* d_out, int out_size)
{
    const float* x  = (const float*)d_in[0];
    const float* Wq = (const float*)d_in[1];
    const float* Wk = (const float*)d_in[2];
    const float* Wv = (const float*)d_in[3];
    const float* Wo = (const float*)d_in[4];
    float* out = (float*)d_out;

    float *pQ, *pK, *pV, *pAO;
    cudaGetSymbolAddress((void**)&pQ,  g_Q);
    cudaGetSymbolAddress((void**)&pK,  g_K);
    cudaGetSymbolAddress((void**)&pV,  g_V);
    cudaGetSymbolAddress((void**)&pAO, g_AO);

    cudaFuncSetAttribute(attn_causal,
                         cudaFuncAttributeMaxDynamicSharedMemorySize, 3 * 64 * 64 * 4);

    dim3 gemm_grid(D_MODEL / 128, MROWS / 128);   // (8, 32)
    sgemm_nt<<<gemm_grid, 256>>>(x, Wq, pQ, MROWS, D_MODEL, D_MODEL);
    sgemm_nt<<<gemm_grid, 256>>>(x, Wk, pK, MROWS, D_MODEL, D_MODEL);
    sgemm_nt<<<gemm_grid, 256>>>(x, Wv, pV, MROWS, D_MODEL, D_MODEL);

    dim3 attn_grid(S_LEN / 64, NHEAD, B_SZ);      // (32, 16, 2)
    attn_causal<<<attn_grid, 256, 3 * 64 * 64 * 4>>>(pQ, pK, pV, pAO);

    sgemm_nt<<<gemm_grid, 256>>>(pAO, Wo, out, MROWS, D_MODEL, D_MODEL);
}

// round 5
// speedup vs baseline: 1.3602x; 1.3602x over previous
#include <cuda_runtime.h>
#include <cuda_bf16.h>
#include <cstdint>
#include <math.h>

// ---------------------------------------------------------------------------
// Problem constants
// ---------------------------------------------------------------------------
#define B_SZ    2
#define S_LEN   2048
#define D_MODEL 1024
#define NHEAD   16
#define DKH     64
#define MROWS   4096
#define KDIM    1024
#define NDIM    1024

// ---------------------------------------------------------------------------
// Scratch (device globals)
// ---------------------------------------------------------------------------
__device__ float g_Q [MROWS * D_MODEL];
__device__ float g_K [MROWS * D_MODEL];
__device__ float g_V [MROWS * D_MODEL];
__device__ float g_AO[MROWS * D_MODEL];

__device__ __align__(16) __nv_bfloat16 g_xh [MROWS * KDIM];
__device__ __align__(16) __nv_bfloat16 g_xl [MROWS * KDIM];
__device__ __align__(16) __nv_bfloat16 g_aoh[MROWS * KDIM];
__device__ __align__(16) __nv_bfloat16 g_aol[MROWS * KDIM];
__device__ __align__(16) __nv_bfloat16 g_wh [4 * KDIM * NDIM];
__device__ __align__(16) __nv_bfloat16 g_wl [4 * KDIM * NDIM];

// ---------------------------------------------------------------------------
// PTX helpers (sm_80-era: cp.async / ldmatrix / mma.sync — valid at compute_100)
// ---------------------------------------------------------------------------
__device__ __forceinline__ uint32_t smem_u32(const void* p) {
    uint32_t a;
    asm("{ .reg .u64 t; cvta.to.shared.u64 t, %1; cvt.u32.u64 %0, t; }"
        : "=r"(a) : "l"(p));
    return a;
}

__device__ __forceinline__ void cp_async16(uint32_t dst, const void* src) {
    asm volatile("cp.async.cg.shared.global [%0], [%1], 16;"
                 :: "r"(dst), "l"(src) : "memory");
}
#define CP_COMMIT() asm volatile("cp.async.commit_group;" ::: "memory")
#define CP_WAIT(n)  asm volatile("cp.async.wait_group %0;" :: "n"(n) : "memory")

#define LDSM4(r, addr) \
    asm volatile("ldmatrix.sync.aligned.m8n8.x4.shared.b16 {%0,%1,%2,%3}, [%4];" \
                 : "=r"((r)[0]), "=r"((r)[1]), "=r"((r)[2]), "=r"((r)[3]) : "r"(addr))

#define MMA16816(d, a, b0v, b1v) \
    asm volatile("mma.sync.aligned.m16n8k16.row.col.f32.bf16.bf16.f32 " \
                 "{%0,%1,%2,%3}, {%4,%5,%6,%7}, {%8,%9}, {%0,%1,%2,%3};" \
                 : "+f"((d)[0]), "+f"((d)[1]), "+f"((d)[2]), "+f"((d)[3]) \
                 : "r"((a)[0]), "r"((a)[1]), "r"((a)[2]), "r"((a)[3]), \
                   "r"(b0v), "r"(b1v))

// ---------------------------------------------------------------------------
// fp32 -> bf16 hi/lo split
// ---------------------------------------------------------------------------
__global__ __launch_bounds__(256)
void split_bf16(const float* __restrict__ in, __nv_bfloat16* __restrict__ hi,
                __nv_bfloat16* __restrict__ lo, int n4)
{
    int i = blockIdx.x * blockDim.x + threadIdx.x;
    if (i >= n4) return;
    float4 v = ((const float4*)in)[i];
    float f[4] = {v.x, v.y, v.z, v.w};
    unsigned short hs[4], ls[4];
    #pragma unroll
    for (int j = 0; j < 4; j++) {
        __nv_bfloat16 h = __float2bfloat16_rn(f[j]);
        float r = f[j] - __bfloat162float(h);
        __nv_bfloat16 l = __float2bfloat16_rn(r);
        hs[j] = __bfloat16_as_ushort(h);
        ls[j] = __bfloat16_as_ushort(l);
    }
    ((ushort4*)hi)[i] = make_ushort4(hs[0], hs[1], hs[2], hs[3]);
    ((ushort4*)lo)[i] = make_ushort4(ls[0], ls[1], ls[2], ls[3]);
}

// ---------------------------------------------------------------------------
// bf16x3-split GEMM via mma.sync:  C[m][n] = sum_k A[m][k] * B[n][k]  (NT)
// CTA tile 128x128x32, 256 threads (8 warps: 2m x 4n), warp tile 64x32,
// per-warp 4x4 m16n8k16 tiles, 3 terms (Ah*Bh + Ah*Bl + Al*Bh).
// smem: 4 tiles/stage (Ah,Al,Bh,Bl) 128 rows x 80B pitch (32 bf16 + pad),
// double-buffered cp.async pipeline. 80B pitch -> conflict-free ldmatrix.
// ---------------------------------------------------------------------------
#define TILE_B   10240           // 128 * 80
#define STAGE_B  (4 * TILE_B)    // 40960
#define GSMEM    (2 * STAGE_B)   // 81920
#define KT       (KDIM / 32)     // 32 k-chunks

__global__ __launch_bounds__(256, 1)
void gemm_bf16x3(const __nv_bfloat16* __restrict__ Agh,
                 const __nv_bfloat16* __restrict__ Agl,
                 const __nv_bfloat16* __restrict__ Bgh,
                 const __nv_bfloat16* __restrict__ Bgl,
                 float* __restrict__ C)
{
    extern __shared__ __align__(128) char smem_raw[];
    const uint32_t smem = smem_u32(smem_raw);

    const int tid    = threadIdx.x;
    const int lane   = tid & 31;
    const int wid    = tid >> 5;
    const int warp_m = wid & 1;        // 0..1 -> m offset 0/64
    const int warp_n = wid >> 1;       // 0..3 -> n offset 0/32/64/96
    const int row0   = blockIdx.y * 128;
    const int col0   = blockIdx.x * 128;

    const __nv_bfloat16* gsrc[4];
    gsrc[0] = Agh; gsrc[1] = Agl; gsrc[2] = Bgh; gsrc[3] = Bgl;
    int gbase[4];
    gbase[0] = row0; gbase[1] = row0; gbase[2] = col0; gbase[3] = col0;

    // per-thread ldmatrix address components
    const uint32_t aoff = (uint32_t)((lane & 15) * 80 + ((lane >> 4) << 4));
    const uint32_t boff = (uint32_t)((((lane >> 3) & 1) * 8 + (lane & 7)) * 80 +
                                     ((lane >> 4) << 4));

    float acc[4][4][4];
    #pragma unroll
    for (int mt = 0; mt < 4; mt++)
        #pragma unroll
        for (int nt = 0; nt < 4; nt++)
            #pragma unroll
            for (int q = 0; q < 4; q++) acc[mt][nt][q] = 0.f;

    const int r_lo = tid >> 2;          // 0..63
    const int k16  = tid & 3;           // 16B chunk within 64B of row data

    // ---- prologue: stage 0 ----
    {
        const uint32_t sb = smem;
        #pragma unroll
        for (int i = 0; i < 8; i++) {
            const int tile = i >> 1;
            const int r    = ((i & 1) << 6) + r_lo;
            const __nv_bfloat16* gp =
                gsrc[tile] + (size_t)(gbase[tile] + r) * KDIM + k16 * 8;
            cp_async16(sb + tile * TILE_B + r * 80 + k16 * 16, gp);
        }
        CP_COMMIT();
    }

    for (int t = 0; t < KT; t++) {
        const int cur = t & 1;
        if (t + 1 < KT) {
            const uint32_t sb = smem + ((t + 1) & 1) * STAGE_B;
            const int k0 = (t + 1) * 32;
            #pragma unroll
            for (int i = 0; i < 8; i++) {
                const int tile = i >> 1;
                const int r    = ((i & 1) << 6) + r_lo;
                const __nv_bfloat16* gp =
                    gsrc[tile] + (size_t)(gbase[tile] + r) * KDIM + k0 + k16 * 8;
                cp_async16(sb + tile * TILE_B + r * 80 + k16 * 16, gp);
            }
            CP_COMMIT();
            CP_WAIT(1);
        } else {
            CP_WAIT(0);
        }
        __syncthreads();

        const uint32_t sb  = smem + cur * STAGE_B;
        const uint32_t Ahs = sb;
        const uint32_t Bhs = sb + 2 * TILE_B;

        #pragma unroll
        for (int kk = 0; kk < 2; kk++) {           // two K16 steps per chunk
            const uint32_t kkb = kk * 32;          // 16 elems * 2B

            uint32_t ah[4][4];
            uint32_t al[4][4];
            uint32_t bh[2][4];
            uint32_t bl[2][4];
            #pragma unroll
            for (int mt = 0; mt < 4; mt++) {
                const uint32_t ad = Ahs + (warp_m * 64 + mt * 16) * 80 + kkb + aoff;
                LDSM4(ah[mt], ad);
                LDSM4(al[mt], ad + TILE_B);
            }
            #pragma unroll
            for (int p = 0; p < 2; p++) {
                const uint32_t bd = Bhs + (warp_n * 32 + p * 16) * 80 + kkb + boff;
                LDSM4(bh[p], bd);
                LDSM4(bl[p], bd + TILE_B);
            }

            #pragma unroll
            for (int mt = 0; mt < 4; mt++)
                #pragma unroll
                for (int nt = 0; nt < 4; nt++) {
                    float* d = acc[mt][nt];
                    const int p = nt >> 1;
                    const int q = nt & 1;
                    MMA16816(d, ah[mt], bh[p][q], bh[p][q + 2]);
                    MMA16816(d, ah[mt], bl[p][q], bl[p][q + 2]);
                    MMA16816(d, al[mt], bh[p][q], bh[p][q + 2]);
                }
        }
        __syncthreads();
    }

    // ---- epilogue: D fragment -> C (fp32) ----
    const int rbase = row0 + warp_m * 64 + (lane >> 2);
    const int cbase = col0 + warp_n * 32 + (lane & 3) * 2;
    #pragma unroll
    for (int mt = 0; mt < 4; mt++) {
        #pragma unroll
        for (int nt = 0; nt < 4; nt++) {
            const int r = rbase + mt * 16;
            const int c = cbase + nt * 8;
            *(float2*)&C[(size_t)r * NDIM + c] =
                make_float2(acc[mt][nt][0], acc[mt][nt][1]);
            *(float2*)&C[(size_t)(r + 8) * NDIM + c] =
                make_float2(acc[mt][nt][2], acc[mt][nt][3]);
        }
    }
}

// ---------------------------------------------------------------------------
// Fused causal flash attention, fp32 (unchanged from passing baseline)
// ---------------------------------------------------------------------------
__global__ __launch_bounds__(256)
void attn_causal(const float* __restrict__ Q, const float* __restrict__ K,
                 const float* __restrict__ V, float* __restrict__ O)
{
    extern __shared__ __align__(16) char sm_raw[];
    float* smem = (float*)sm_raw;
    float* Qs = smem;
    float* KP = smem + 64 * 64;
    float* Vs = smem + 2 * 64 * 64;

    const int tid = threadIdx.x;
    const int tx  = tid & 15;
    const int ty  = tid >> 4;
    const int qt  = blockIdx.x;
    const int h   = blockIdx.y;
    const int b   = blockIdx.z;
    const int q0  = qt * 64;
    const size_t headoff = (size_t)h * DKH;

    #pragma unroll
    for (int it = 0; it < 4; it++) {
        int idx = tid + it * 256;
        int m   = idx >> 4;
        int d4  = (idx & 15) << 2;
        float4 v = *(const float4*)&Q[((size_t)(b * S_LEN + q0 + m)) * D_MODEL + headoff + d4];
        Qs[(d4+0)*64 + m] = v.x * 0.125f;
        Qs[(d4+1)*64 + m] = v.y * 0.125f;
        Qs[(d4+2)*64 + m] = v.z * 0.125f;
        Qs[(d4+3)*64 + m] = v.w * 0.125f;
    }

    float o[4][4];
    #pragma unroll
    for (int i = 0; i < 4; i++)
        #pragma unroll
        for (int j = 0; j < 4; j++) o[i][j] = 0.f;
    float mi[4] = {-1e30f, -1e30f, -1e30f, -1e30f};
    float li[4] = {0.f, 0.f, 0.f, 0.f};

    for (int jt = 0; jt <= qt; jt++) {
        __syncthreads();
        const int k0 = jt * 64;
        #pragma unroll
        for (int it = 0; it < 4; it++) {
            int idx = tid + it * 256;
            int n   = idx >> 4;
            int d4  = (idx & 15) << 2;
            float4 vk = *(const float4*)&K[((size_t)(b * S_LEN + k0 + n)) * D_MODEL + headoff + d4];
            KP[(d4+0)*64 + n] = vk.x;
            KP[(d4+1)*64 + n] = vk.y;
            KP[(d4+2)*64 + n] = vk.z;
            KP[(d4+3)*64 + n] = vk.w;
            float4 vv = *(const float4*)&V[((size_t)(b * S_LEN + k0 + n)) * D_MODEL + headoff + d4];
            *(float4*)&Vs[n * 64 + d4] = vv;
        }
        __syncthreads();

        float s[4][4];
        #pragma unroll
        for (int i = 0; i < 4; i++)
            #pragma unroll
            for (int j = 0; j < 4; j++) s[i][j] = 0.f;
        #pragma unroll 8
        for (int d = 0; d < 64; d++) {
            float4 a4 = *(const float4*)&Qs[d * 64 + ty * 4];
            float4 b4 = *(const float4*)&KP[d * 64 + tx * 4];
            float a[4] = {a4.x, a4.y, a4.z, a4.w};
            float bb[4] = {b4.x, b4.y, b4.z, b4.w};
            #pragma unroll
            for (int i = 0; i < 4; i++)
                #pragma unroll
                for (int j = 0; j < 4; j++)
                    s[i][j] = fmaf(a[i], bb[j], s[i][j]);
        }

        if (jt == qt) {
            #pragma unroll
            for (int i = 0; i < 4; i++)
                #pragma unroll
                for (int j = 0; j < 4; j++)
                    if (tx * 4 + j > ty * 4 + i) s[i][j] = -1e30f;
        }

        #pragma unroll
        for (int i = 0; i < 4; i++) {
            float rmax = fmaxf(fmaxf(s[i][0], s[i][1]), fmaxf(s[i][2], s[i][3]));
            #pragma unroll
            for (int off = 8; off >= 1; off >>= 1)
                rmax = fmaxf(rmax, __shfl_xor_sync(0xffffffffu, rmax, off));
            float mnew  = fmaxf(mi[i], rmax);
            float alpha = __expf(mi[i] - mnew);
            float rsum  = 0.f;
            #pragma unroll
            for (int j = 0; j < 4; j++) {
                s[i][j] = __expf(s[i][j] - mnew);
                rsum += s[i][j];
            }
            #pragma unroll
            for (int off = 8; off >= 1; off >>= 1)
                rsum += __shfl_xor_sync(0xffffffffu, rsum, off);
            li[i] = li[i] * alpha + rsum;
            mi[i] = mnew;
            #pragma unroll
            for (int j = 0; j < 4; j++) o[i][j] *= alpha;
        }

        __syncthreads();
        #pragma unroll
        for (int j = 0; j < 4; j++) {
            float4 pv = make_float4(s[0][j], s[1][j], s[2][j], s[3][j]);
            *(float4*)&KP[(tx * 4 + j) * 64 + ty * 4] = pv;
        }
        __syncthreads();

        #pragma unroll 8
        for (int n = 0; n < 64; n++) {
            float4 p4 = *(const float4*)&KP[n * 64 + ty * 4];
            float4 v4 = *(const float4*)&Vs[n * 64 + tx * 4];
            float p[4] = {p4.x, p4.y, p4.z, p4.w};
            float vv[4] = {v4.x, v4.y, v4.z, v4.w};
            #pragma unroll
            for (int i = 0; i < 4; i++)
                #pragma unroll
                for (int j = 0; j < 4; j++)
                    o[i][j] = fmaf(p[i], vv[j], o[i][j]);
        }
    }

    #pragma unroll
    for (int i = 0; i < 4; i++) {
        float inv = 1.f / li[i];
        float4 v = make_float4(o[i][0] * inv, o[i][1] * inv,
                               o[i][2] * inv, o[i][3] * inv);
        size_t base = ((size_t)(b * S_LEN + q0 + ty * 4 + i)) * D_MODEL + headoff + tx * 4;
        *(float4*)&O[base] = v;
    }
}

// ---------------------------------------------------------------------------
// Launch
// ---------------------------------------------------------------------------
extern "C" void kernel_launch(void* const* d_in, const int* in_sizes, int n_in,
                              void* d_out, int out_size)
{
    const float* x  = (const float*)d_in[0];
    float* out = (float*)d_out;

    float *pQ, *pK, *pV, *pAO;
    __nv_bfloat16 *pxh, *pxl, *paoh, *paol, *pwh, *pwl;
    cudaGetSymbolAddress((void**)&pQ,   g_Q);
    cudaGetSymbolAddress((void**)&pK,   g_K);
    cudaGetSymbolAddress((void**)&pV,   g_V);
    cudaGetSymbolAddress((void**)&pAO,  g_AO);
    cudaGetSymbolAddress((void**)&pxh,  g_xh);
    cudaGetSymbolAddress((void**)&pxl,  g_xl);
    cudaGetSymbolAddress((void**)&paoh, g_aoh);
    cudaGetSymbolAddress((void**)&paol, g_aol);
    cudaGetSymbolAddress((void**)&pwh,  g_wh);
    cudaGetSymbolAddress((void**)&pwl,  g_wl);

    cudaFuncSetAttribute(gemm_bf16x3,
                         cudaFuncAttributeMaxDynamicSharedMemorySize, GSMEM);
    cudaFuncSetAttribute(attn_causal,
                         cudaFuncAttributeMaxDynamicSharedMemorySize, 3 * 64 * 64 * 4);

    // 1) split inputs to bf16 hi/lo
    split_bf16<<<(MROWS * KDIM / 4 + 255) / 256, 256>>>(x, pxh, pxl, MROWS * KDIM / 4);
    for (int w = 0; w < 4; w++)
        split_bf16<<<(KDIM * NDIM / 4 + 255) / 256, 256>>>(
            (const float*)d_in[1 + w],
            pwh + (size_t)w * KDIM * NDIM, pwl + (size_t)w * KDIM * NDIM,
            KDIM * NDIM / 4);

    // 2) Q/K/V projections (tensor cores)
    dim3 ggrid(NDIM / 128, MROWS / 128);   // (8, 32)
    gemm_bf16x3<<<ggrid, 256, GSMEM>>>(pxh, pxl, pwh + 0 * (size_t)KDIM * NDIM,
                                       pwl + 0 * (size_t)KDIM * NDIM, pQ);
    gemm_bf16x3<<<ggrid, 256, GSMEM>>>(pxh, pxl, pwh + 1 * (size_t)KDIM * NDIM,
                                       pwl + 1 * (size_t)KDIM * NDIM, pK);
    gemm_bf16x3<<<ggrid, 256, GSMEM>>>(pxh, pxl, pwh + 2 * (size_t)KDIM * NDIM,
                                       pwl + 2 * (size_t)KDIM * NDIM, pV);

    // 3) fused causal attention (fp32)
    dim3 attn_grid(S_LEN / 64, NHEAD, B_SZ);
    attn_causal<<<attn_grid, 256, 3 * 64 * 64 * 4>>>(pQ, pK, pV, pAO);

    // 4) output projection
    split_bf16<<<(MROWS * KDIM / 4 + 255) / 256, 256>>>(pAO, paoh, paol, MROWS * KDIM / 4);
    gemm_bf16x3<<<ggrid, 256, GSMEM>>>(paoh, paol, pwh + 3 * (size_t)KDIM * NDIM,
                                       pwl + 3 * (size_t)KDIM * NDIM, out);
}

// round 6
// speedup vs baseline: 2.4961x; 1.8352x over previous
#include <cuda_runtime.h>
#include <cuda_bf16.h>
#include <cstdint>
#include <math.h>

// ---------------------------------------------------------------------------
// Problem constants
// ---------------------------------------------------------------------------
#define B_SZ    2
#define S_LEN   2048
#define D_MODEL 1024
#define NHEAD   16
#define DKH     64
#define MROWS   4096
#define KDIM    1024
#define NDIM    1024
#define NQT     (S_LEN / 128)     // 16 q-tiles

// ---------------------------------------------------------------------------
// Scratch (device globals)
// ---------------------------------------------------------------------------
__device__ float g_Q [MROWS * D_MODEL];
__device__ float g_K [MROWS * D_MODEL];
__device__ float g_V [MROWS * D_MODEL];
__device__ float g_AO[MROWS * D_MODEL];

__device__ __align__(16) __nv_bfloat16 g_xh [MROWS * KDIM];
__device__ __align__(16) __nv_bfloat16 g_xl [MROWS * KDIM];
__device__ __align__(16) __nv_bfloat16 g_aoh[MROWS * KDIM];
__device__ __align__(16) __nv_bfloat16 g_aol[MROWS * KDIM];
__device__ __align__(16) __nv_bfloat16 g_wh [4 * KDIM * NDIM];
__device__ __align__(16) __nv_bfloat16 g_wl [4 * KDIM * NDIM];

__device__ __align__(16) __nv_bfloat16 g_qh [MROWS * D_MODEL];
__device__ __align__(16) __nv_bfloat16 g_ql [MROWS * D_MODEL];
__device__ __align__(16) __nv_bfloat16 g_kh [MROWS * D_MODEL];
__device__ __align__(16) __nv_bfloat16 g_kl [MROWS * D_MODEL];
__device__ __align__(16) __nv_bfloat16 g_vh [MROWS * D_MODEL];
__device__ __align__(16) __nv_bfloat16 g_vl [MROWS * D_MODEL];

// ---------------------------------------------------------------------------
// PTX helpers (sm_80-era, valid at compute_100)
// ---------------------------------------------------------------------------
__device__ __forceinline__ uint32_t smem_u32(const void* p) {
    uint32_t a;
    asm("{ .reg .u64 t; cvta.to.shared.u64 t, %1; cvt.u32.u64 %0, t; }"
        : "=r"(a) : "l"(p));
    return a;
}

__device__ __forceinline__ void cp_async16(uint32_t dst, const void* src) {
    asm volatile("cp.async.cg.shared.global [%0], [%1], 16;"
                 :: "r"(dst), "l"(src) : "memory");
}
#define CP_COMMIT() asm volatile("cp.async.commit_group;" ::: "memory")
#define CP_WAIT(n)  asm volatile("cp.async.wait_group %0;" :: "n"(n) : "memory")

#define LDSM4(r, addr) \
    asm volatile("ldmatrix.sync.aligned.m8n8.x4.shared.b16 {%0,%1,%2,%3}, [%4];" \
                 : "=r"((r)[0]), "=r"((r)[1]), "=r"((r)[2]), "=r"((r)[3]) : "r"(addr))

#define LDSM4T(r, addr) \
    asm volatile("ldmatrix.sync.aligned.m8n8.x4.trans.shared.b16 {%0,%1,%2,%3}, [%4];" \
                 : "=r"((r)[0]), "=r"((r)[1]), "=r"((r)[2]), "=r"((r)[3]) : "r"(addr))

#define MMA16816(d, a, b0v, b1v) \
    asm volatile("mma.sync.aligned.m16n8k16.row.col.f32.bf16.bf16.f32 " \
                 "{%0,%1,%2,%3}, {%4,%5,%6,%7}, {%8,%9}, {%0,%1,%2,%3};" \
                 : "+f"((d)[0]), "+f"((d)[1]), "+f"((d)[2]), "+f"((d)[3]) \
                 : "r"((a)[0]), "r"((a)[1]), "r"((a)[2]), "r"((a)[3]), \
                   "r"(b0v), "r"(b1v))

// pack two fp32 -> bf16x2 (lo = second operand)
__device__ __forceinline__ uint32_t bf2x(float hi, float lo) {
    uint32_t d;
    asm("cvt.rn.bf16x2.f32 %0, %1, %2;" : "=r"(d) : "f"(hi), "f"(lo));
    return d;
}
__device__ __forceinline__ float bf_round(float x) {
    return __bfloat162float(__float2bfloat16_rn(x));
}

// ---------------------------------------------------------------------------
// fp32 -> bf16 hi/lo split (with optional scale)
// ---------------------------------------------------------------------------
__global__ __launch_bounds__(256)
void split_bf16(const float* __restrict__ in, __nv_bfloat16* __restrict__ hi,
                __nv_bfloat16* __restrict__ lo, int n4, float scale)
{
    int i = blockIdx.x * blockDim.x + threadIdx.x;
    if (i >= n4) return;
    float4 v = ((const float4*)in)[i];
    float f[4] = {v.x * scale, v.y * scale, v.z * scale, v.w * scale};
    unsigned short hs[4], ls[4];
    #pragma unroll
    for (int j = 0; j < 4; j++) {
        __nv_bfloat16 h = __float2bfloat16_rn(f[j]);
        float r = f[j] - __bfloat162float(h);
        __nv_bfloat16 l = __float2bfloat16_rn(r);
        hs[j] = __bfloat16_as_ushort(h);
        ls[j] = __bfloat16_as_ushort(l);
    }
    ((ushort4*)hi)[i] = make_ushort4(hs[0], hs[1], hs[2], hs[3]);
    ((ushort4*)lo)[i] = make_ushort4(ls[0], ls[1], ls[2], ls[3]);
}

// ---------------------------------------------------------------------------
// bf16x3-split GEMM via mma.sync (unchanged, passing @ rel_err 1.45e-5)
// ---------------------------------------------------------------------------
#define TILE_B   10240
#define STAGE_B  (4 * TILE_B)
#define GSMEM    (2 * STAGE_B)
#define KT       (KDIM / 32)

__global__ __launch_bounds__(256, 1)
void gemm_bf16x3(const __nv_bfloat16* __restrict__ Agh,
                 const __nv_bfloat16* __restrict__ Agl,
                 const __nv_bfloat16* __restrict__ Bgh,
                 const __nv_bfloat16* __restrict__ Bgl,
                 float* __restrict__ C)
{
    extern __shared__ __align__(128) char smem_raw[];
    const uint32_t smem = smem_u32(smem_raw);

    const int tid    = threadIdx.x;
    const int lane   = tid & 31;
    const int wid    = tid >> 5;
    const int warp_m = wid & 1;
    const int warp_n = wid >> 1;
    const int row0   = blockIdx.y * 128;
    const int col0   = blockIdx.x * 128;

    const __nv_bfloat16* gsrc[4];
    gsrc[0] = Agh; gsrc[1] = Agl; gsrc[2] = Bgh; gsrc[3] = Bgl;
    int gbase[4];
    gbase[0] = row0; gbase[1] = row0; gbase[2] = col0; gbase[3] = col0;

    const uint32_t aoff = (uint32_t)((lane & 15) * 80 + ((lane >> 4) << 4));
    const uint32_t boff = (uint32_t)((((lane >> 3) & 1) * 8 + (lane & 7)) * 80 +
                                     ((lane >> 4) << 4));

    float acc[4][4][4];
    #pragma unroll
    for (int mt = 0; mt < 4; mt++)
        #pragma unroll
        for (int nt = 0; nt < 4; nt++)
            #pragma unroll
            for (int q = 0; q < 4; q++) acc[mt][nt][q] = 0.f;

    const int r_lo = tid >> 2;
    const int k16  = tid & 3;

    {
        const uint32_t sb = smem;
        #pragma unroll
        for (int i = 0; i < 8; i++) {
            const int tile = i >> 1;
            const int r    = ((i & 1) << 6) + r_lo;
            const __nv_bfloat16* gp =
                gsrc[tile] + (size_t)(gbase[tile] + r) * KDIM + k16 * 8;
            cp_async16(sb + tile * TILE_B + r * 80 + k16 * 16, gp);
        }
        CP_COMMIT();
    }

    for (int t = 0; t < KT; t++) {
        const int cur = t & 1;
        if (t + 1 < KT) {
            const uint32_t sb = smem + ((t + 1) & 1) * STAGE_B;
            const int k0 = (t + 1) * 32;
            #pragma unroll
            for (int i = 0; i < 8; i++) {
                const int tile = i >> 1;
                const int r    = ((i & 1) << 6) + r_lo;
                const __nv_bfloat16* gp =
                    gsrc[tile] + (size_t)(gbase[tile] + r) * KDIM + k0 + k16 * 8;
                cp_async16(sb + tile * TILE_B + r * 80 + k16 * 16, gp);
            }
            CP_COMMIT();
            CP_WAIT(1);
        } else {
            CP_WAIT(0);
        }
        __syncthreads();

        const uint32_t sb  = smem + cur * STAGE_B;
        const uint32_t Ahs = sb;
        const uint32_t Bhs = sb + 2 * TILE_B;

        #pragma unroll
        for (int kk = 0; kk < 2; kk++) {
            const uint32_t kkb = kk * 32;
            uint32_t ah[4][4];
            uint32_t al[4][4];
            uint32_t bh[2][4];
            uint32_t bl[2][4];
            #pragma unroll
            for (int mt = 0; mt < 4; mt++) {
                const uint32_t ad = Ahs + (warp_m * 64 + mt * 16) * 80 + kkb + aoff;
                LDSM4(ah[mt], ad);
                LDSM4(al[mt], ad + TILE_B);
            }
            #pragma unroll
            for (int p = 0; p < 2; p++) {
                const uint32_t bd = Bhs + (warp_n * 32 + p * 16) * 80 + kkb + boff;
                LDSM4(bh[p], bd);
                LDSM4(bl[p], bd + TILE_B);
            }
            #pragma unroll
            for (int mt = 0; mt < 4; mt++)
                #pragma unroll
                for (int nt = 0; nt < 4; nt++) {
                    float* d = acc[mt][nt];
                    const int p = nt >> 1;
                    const int q = nt & 1;
                    MMA16816(d, ah[mt], bh[p][q], bh[p][q + 2]);
                    MMA16816(d, ah[mt], bl[p][q], bl[p][q + 2]);
                    MMA16816(d, al[mt], bh[p][q], bh[p][q + 2]);
                }
        }
        __syncthreads();
    }

    const int rbase = row0 + warp_m * 64 + (lane >> 2);
    const int cbase = col0 + warp_n * 32 + (lane & 3) * 2;
    #pragma unroll
    for (int mt = 0; mt < 4; mt++) {
        #pragma unroll
        for (int nt = 0; nt < 4; nt++) {
            const int r = rbase + mt * 16;
            const int c = cbase + nt * 8;
            *(float2*)&C[(size_t)r * NDIM + c] =
                make_float2(acc[mt][nt][0], acc[mt][nt][1]);
            *(float2*)&C[(size_t)(r + 8) * NDIM + c] =
                make_float2(acc[mt][nt][2], acc[mt][nt][3]);
        }
    }
}

// ---------------------------------------------------------------------------
// Tensor-core causal flash attention, bf16x3 split.
// Grid (NQT, H, B), 256 threads (8 warps x 16 query rows = 128-row q-tile).
// K/V streamed in 64-key chunks, double-buffered cp.async.
// Q (pre-scaled) kept in registers as A-fragments. V via ldmatrix.trans.
// ---------------------------------------------------------------------------
#define APITCH  144                 // 64 bf16 = 128B data + 16B pad
#define KV_TILE (64 * APITCH)       // 9216
#define ASTAGE  (4 * KV_TILE)       // Kh Kl Vh Vl = 36864
#define ASMEM   (2 * ASTAGE)        // 73728

__global__ __launch_bounds__(256, 1)
void attn_mma(const __nv_bfloat16* __restrict__ Qh_, const __nv_bfloat16* __restrict__ Ql_,
              const __nv_bfloat16* __restrict__ Kh_, const __nv_bfloat16* __restrict__ Kl_,
              const __nv_bfloat16* __restrict__ Vh_, const __nv_bfloat16* __restrict__ Vl_,
              float* __restrict__ O)
{
    extern __shared__ __align__(128) char smx[];
    const uint32_t smem = smem_u32(smx);
    const int tid  = threadIdx.x;
    const int lane = tid & 31;
    const int w    = tid >> 5;
    const int qt   = (NQT - 1) - blockIdx.x;   // heavy tiles first
    const int h    = blockIdx.y;
    const int b    = blockIdx.z;
    const int q0   = qt * 128;
    const int hbase = h * 64;

    const uint32_t aoff = (uint32_t)((lane & 15) * APITCH + ((lane >> 4) << 4));
    const uint32_t boff = (uint32_t)((((lane >> 3) & 1) * 8 + (lane & 7)) * APITCH +
                                     ((lane >> 4) << 4));
    const uint32_t voff = aoff;   // same pattern for trans-ldsm on [key][dim]

    // ---- load Q hi/lo (128 x 64) into stage0 area, then to registers ----
    {
        const int r  = tid >> 1;               // 0..127
        const int c4 = (tid & 1) * 4;          // chunks c4..c4+3
        const size_t gq = ((size_t)(b * S_LEN + q0 + r)) * D_MODEL + hbase;
        const uint32_t d0 = smem + ((r >= 64) ? KV_TILE : 0) + (r & 63) * APITCH;
        #pragma unroll
        for (int j = 0; j < 4; j++) {
            cp_async16(d0 + (c4 + j) * 16, Qh_ + gq + (c4 + j) * 8);
            cp_async16(d0 + 2 * KV_TILE + (c4 + j) * 16, Ql_ + gq + (c4 + j) * 8);
        }
        CP_COMMIT();
        CP_WAIT(0);
    }
    __syncthreads();

    uint32_t qh[4][4], ql[4][4];
    {
        const uint32_t qtb = smem + ((w >= 4) ? KV_TILE : 0) + (w & 3) * 16 * APITCH;
        #pragma unroll
        for (int ks = 0; ks < 4; ks++) {
            LDSM4(qh[ks], qtb + ks * 32 + aoff);
            LDSM4(ql[ks], qtb + 2 * KV_TILE + ks * 32 + aoff);
        }
    }
    __syncthreads();   // Q consumed; stage0 free for K/V

    const __nv_bfloat16* kvsrc[4];
    kvsrc[0] = Kh_; kvsrc[1] = Kl_; kvsrc[2] = Vh_; kvsrc[3] = Vl_;

    float o[8][4];
    #pragma unroll
    for (int nt = 0; nt < 8; nt++)
        #pragma unroll
        for (int e = 0; e < 4; e++) o[nt][e] = 0.f;
    float mi0 = -1e30f, mi1 = -1e30f, li0 = 0.f, li1 = 0.f;

    const int nch = 2 * (qt + 1);
    const int r_lo = tid >> 3;                 // 0..31
    const int ch8  = tid & 7;

    // prologue: chunk 0
    {
        const uint32_t sb = smem;
        #pragma unroll
        for (int i = 0; i < 8; i++) {
            const int tile = i >> 1;
            const int r    = ((i & 1) << 5) + r_lo;
            const __nv_bfloat16* gp =
                kvsrc[tile] + ((size_t)(b * S_LEN + r)) * D_MODEL + hbase + ch8 * 8;
            cp_async16(sb + tile * KV_TILE + r * APITCH + ch8 * 16, gp);
        }
        CP_COMMIT();
    }

    for (int c = 0; c < nch; c++) {
        if (c + 1 < nch) {
            const uint32_t sb = smem + ((c + 1) & 1) * ASTAGE;
            const int k0 = (c + 1) * 64;
            #pragma unroll
            for (int i = 0; i < 8; i++) {
                const int tile = i >> 1;
                const int r    = ((i & 1) << 5) + r_lo;
                const __nv_bfloat16* gp =
                    kvsrc[tile] + ((size_t)(b * S_LEN + k0 + r)) * D_MODEL + hbase + ch8 * 8;
                cp_async16(sb + tile * KV_TILE + r * APITCH + ch8 * 16, gp);
            }
            CP_COMMIT();
            CP_WAIT(1);
        } else {
            CP_WAIT(0);
        }
        __syncthreads();

        const int c0 = c * 64;
        const uint32_t sb  = smem + (c & 1) * ASTAGE;
        const uint32_t Khs = sb;
        const uint32_t Kls = sb + KV_TILE;
        const uint32_t Vhs = sb + 2 * KV_TILE;
        const uint32_t Vls = sb + 3 * KV_TILE;

        // ---- scores: S = Q K^T ----
        float s[8][4];
        #pragma unroll
        for (int nt = 0; nt < 8; nt++)
            #pragma unroll
            for (int e = 0; e < 4; e++) s[nt][e] = 0.f;

        #pragma unroll
        for (int ks = 0; ks < 4; ks++) {
            uint32_t kh[4][4], kl[4][4];
            #pragma unroll
            for (int p = 0; p < 4; p++) {
                LDSM4(kh[p], Khs + p * 16 * APITCH + ks * 32 + boff);
                LDSM4(kl[p], Kls + p * 16 * APITCH + ks * 32 + boff);
            }
            #pragma unroll
            for (int nt = 0; nt < 8; nt++) {
                const int p = nt >> 1;
                const int q = nt & 1;
                MMA16816(s[nt], qh[ks], kh[p][q], kh[p][q + 2]);
                MMA16816(s[nt], ql[ks], kh[p][q], kh[p][q + 2]);
                MMA16816(s[nt], qh[ks], kl[p][q], kl[p][q + 2]);
            }
        }

        // ---- causal mask (only diagonal chunks) ----
        if (c0 >= q0) {
            const int qr0 = q0 + w * 16 + (lane >> 2);
            #pragma unroll
            for (int nt = 0; nt < 8; nt++)
                #pragma unroll
                for (int e = 0; e < 4; e++) {
                    const int key = c0 + nt * 8 + 2 * (lane & 3) + (e & 1);
                    const int qr  = qr0 + (e >> 1) * 8;
                    if (key > qr) s[nt][e] = -1e30f;
                }
        }

        // ---- online softmax (rows r0 = lane>>2 and r0+8) ----
        float rmax0 = -1e30f, rmax1 = -1e30f;
        #pragma unroll
        for (int nt = 0; nt < 8; nt++) {
            rmax0 = fmaxf(rmax0, fmaxf(s[nt][0], s[nt][1]));
            rmax1 = fmaxf(rmax1, fmaxf(s[nt][2], s[nt][3]));
        }
        rmax0 = fmaxf(rmax0, __shfl_xor_sync(0xffffffffu, rmax0, 1));
        rmax0 = fmaxf(rmax0, __shfl_xor_sync(0xffffffffu, rmax0, 2));
        rmax1 = fmaxf(rmax1, __shfl_xor_sync(0xffffffffu, rmax1, 1));
        rmax1 = fmaxf(rmax1, __shfl_xor_sync(0xffffffffu, rmax1, 2));

        const float mnew0 = fmaxf(mi0, rmax0);
        const float mnew1 = fmaxf(mi1, rmax1);
        const float alpha0 = __expf(mi0 - mnew0);
        const float alpha1 = __expf(mi1 - mnew1);
        mi0 = mnew0; mi1 = mnew1;

        float rsum0 = 0.f, rsum1 = 0.f;
        #pragma unroll
        for (int nt = 0; nt < 8; nt++) {
            s[nt][0] = __expf(s[nt][0] - mnew0);
            s[nt][1] = __expf(s[nt][1] - mnew0);
            s[nt][2] = __expf(s[nt][2] - mnew1);
            s[nt][3] = __expf(s[nt][3] - mnew1);
            rsum0 += s[nt][0] + s[nt][1];
            rsum1 += s[nt][2] + s[nt][3];
        }
        rsum0 += __shfl_xor_sync(0xffffffffu, rsum0, 1);
        rsum0 += __shfl_xor_sync(0xffffffffu, rsum0, 2);
        rsum1 += __shfl_xor_sync(0xffffffffu, rsum1, 1);
        rsum1 += __shfl_xor_sync(0xffffffffu, rsum1, 2);
        li0 = li0 * alpha0 + rsum0;
        li1 = li1 * alpha1 + rsum1;

        #pragma unroll
        for (int nt = 0; nt < 8; nt++) {
            o[nt][0] *= alpha0; o[nt][1] *= alpha0;
            o[nt][2] *= alpha1; o[nt][3] *= alpha1;
        }

        // ---- O += P V  (P split hi/lo in registers) ----
        #pragma unroll
        for (int kb = 0; kb < 4; kb++) {
            uint32_t ph[4], pl[4];
            {
                const float* s0 = s[2 * kb];
                const float* s1 = s[2 * kb + 1];
                float h00 = bf_round(s0[0]), h01 = bf_round(s0[1]);
                float h02 = bf_round(s0[2]), h03 = bf_round(s0[3]);
                float h10 = bf_round(s1[0]), h11 = bf_round(s1[1]);
                float h12 = bf_round(s1[2]), h13 = bf_round(s1[3]);
                ph[0] = bf2x(s0[1], s0[0]);
                ph[1] = bf2x(s0[3], s0[2]);
                ph[2] = bf2x(s1[1], s1[0]);
                ph[3] = bf2x(s1[3], s1[2]);
                pl[0] = bf2x(s0[1] - h01, s0[0] - h00);
                pl[1] = bf2x(s0[3] - h03, s0[2] - h02);
                pl[2] = bf2x(s1[1] - h11, s1[0] - h10);
                pl[3] = bf2x(s1[3] - h13, s1[2] - h12);
            }
            #pragma unroll
            for (int dt = 0; dt < 4; dt++) {
                uint32_t vh[4], vl[4];
                LDSM4T(vh, Vhs + kb * 16 * APITCH + dt * 32 + voff);
                LDSM4T(vl, Vls + kb * 16 * APITCH + dt * 32 + voff);
                #pragma unroll
                for (int q = 0; q < 2; q++) {
                    const int nt = dt * 2 + q;
                    MMA16816(o[nt], ph, vh[2 * q], vh[2 * q + 1]);
                    MMA16816(o[nt], pl, vh[2 * q], vh[2 * q + 1]);
                    MMA16816(o[nt], ph, vl[2 * q], vl[2 * q + 1]);
                }
            }
        }
        __syncthreads();
    }

    // ---- epilogue: normalize, write O[b][q][h*64+dim] ----
    const float inv0 = 1.f / li0;
    const float inv1 = 1.f / li1;
    const int qr0 = q0 + w * 16 + (lane >> 2);
    const int cb  = hbase + 2 * (lane & 3);
    #pragma unroll
    for (int nt = 0; nt < 8; nt++) {
        *(float2*)&O[((size_t)(b * S_LEN + qr0)) * D_MODEL + cb + nt * 8] =
            make_float2(o[nt][0] * inv0, o[nt][1] * inv0);
        *(float2*)&O[((size_t)(b * S_LEN + qr0 + 8)) * D_MODEL + cb + nt * 8] =
            make_float2(o[nt][2] * inv1, o[nt][3] * inv1);
    }
}

// ---------------------------------------------------------------------------
// Launch
// ---------------------------------------------------------------------------
extern "C" void kernel_launch(void* const* d_in, const int* in_sizes, int n_in,
                              void* d_out, int out_size)
{
    const float* x  = (const float*)d_in[0];
    float* out = (float*)d_out;

    float *pQ, *pK, *pV, *pAO;
    __nv_bfloat16 *pxh, *pxl, *paoh, *paol, *pwh, *pwl;
    __nv_bfloat16 *pqh, *pql, *pkh, *pkl, *pvh, *pvl;
    cudaGetSymbolAddress((void**)&pQ,   g_Q);
    cudaGetSymbolAddress((void**)&pK,   g_K);
    cudaGetSymbolAddress((void**)&pV,   g_V);
    cudaGetSymbolAddress((void**)&pAO,  g_AO);
    cudaGetSymbolAddress((void**)&pxh,  g_xh);
    cudaGetSymbolAddress((void**)&pxl,  g_xl);
    cudaGetSymbolAddress((void**)&paoh, g_aoh);
    cudaGetSymbolAddress((void**)&paol, g_aol);
    cudaGetSymbolAddress((void**)&pwh,  g_wh);
    cudaGetSymbolAddress((void**)&pwl,  g_wl);
    cudaGetSymbolAddress((void**)&pqh,  g_qh);
    cudaGetSymbolAddress((void**)&pql,  g_ql);
    cudaGetSymbolAddress((void**)&pkh,  g_kh);
    cudaGetSymbolAddress((void**)&pkl,  g_kl);
    cudaGetSymbolAddress((void**)&pvh,  g_vh);
    cudaGetSymbolAddress((void**)&pvl,  g_vl);

    cudaFuncSetAttribute(gemm_bf16x3,
                         cudaFuncAttributeMaxDynamicSharedMemorySize, GSMEM);
    cudaFuncSetAttribute(attn_mma,
                         cudaFuncAttributeMaxDynamicSharedMemorySize, ASMEM);

    const int n4e = MROWS * KDIM / 4;
    const int n4w = KDIM * NDIM / 4;

    // 1) split inputs
    split_bf16<<<(n4e + 255) / 256, 256>>>(x, pxh, pxl, n4e, 1.f);
    for (int w = 0; w < 4; w++)
        split_bf16<<<(n4w + 255) / 256, 256>>>(
            (const float*)d_in[1 + w],
            pwh + (size_t)w * KDIM * NDIM, pwl + (size_t)w * KDIM * NDIM,
            n4w, 1.f);

    // 2) Q/K/V projections
    dim3 ggrid(NDIM / 128, MROWS / 128);
    gemm_bf16x3<<<ggrid, 256, GSMEM>>>(pxh, pxl, pwh + 0 * (size_t)KDIM * NDIM,
                                       pwl + 0 * (size_t)KDIM * NDIM, pQ);
    gemm_bf16x3<<<ggrid, 256, GSMEM>>>(pxh, pxl, pwh + 1 * (size_t)KDIM * NDIM,
                                       pwl + 1 * (size_t)KDIM * NDIM, pK);
    gemm_bf16x3<<<ggrid, 256, GSMEM>>>(pxh, pxl, pwh + 2 * (size_t)KDIM * NDIM,
                                       pwl + 2 * (size_t)KDIM * NDIM, pV);

    // 3) split Q (scaled by 1/sqrt(dk)), K, V
    split_bf16<<<(n4e + 255) / 256, 256>>>(pQ, pqh, pql, n4e, 0.125f);
    split_bf16<<<(n4e + 255) / 256, 256>>>(pK, pkh, pkl, n4e, 1.f);
    split_bf16<<<(n4e + 255) / 256, 256>>>(pV, pvh, pvl, n4e, 1.f);

    // 4) tensor-core causal attention
    dim3 agrid(NQT, NHEAD, B_SZ);
    attn_mma<<<agrid, 256, ASMEM>>>(pqh, pql, pkh, pkl, pvh, pvl, pAO);

    // 5) output projection
    split_bf16<<<(n4e + 255) / 256, 256>>>(pAO, paoh, paol, n4e, 1.f);
    gemm_bf16x3<<<ggrid, 256, GSMEM>>>(paoh, paol, pwh + 3 * (size_t)KDIM * NDIM,
                                       pwl + 3 * (size_t)KDIM * NDIM, out);
}

// round 7
// speedup vs baseline: 2.5066x; 1.0042x over previous
#include <cuda_runtime.h>
#include <cuda_bf16.h>
#include <cstdint>
#include <math.h>

// ---------------------------------------------------------------------------
// Problem constants
// ---------------------------------------------------------------------------
#define B_SZ    2
#define S_LEN   2048
#define D_MODEL 1024
#define NHEAD   16
#define DKH     64
#define MROWS   4096
#define KDIM    1024
#define NDIM    1024
#define NQT     (S_LEN / 128)     // 16 q-tiles

// ---------------------------------------------------------------------------
// Scratch (device globals)
// ---------------------------------------------------------------------------
__device__ float g_Q [MROWS * D_MODEL];
__device__ float g_K [MROWS * D_MODEL];
__device__ float g_V [MROWS * D_MODEL];
__device__ float g_AO[MROWS * D_MODEL];

__device__ __align__(16) __nv_bfloat16 g_xh [MROWS * KDIM];
__device__ __align__(16) __nv_bfloat16 g_xl [MROWS * KDIM];
__device__ __align__(16) __nv_bfloat16 g_aoh[MROWS * KDIM];
__device__ __align__(16) __nv_bfloat16 g_aol[MROWS * KDIM];
__device__ __align__(16) __nv_bfloat16 g_wh [4 * KDIM * NDIM];
__device__ __align__(16) __nv_bfloat16 g_wl [4 * KDIM * NDIM];

__device__ __align__(16) __nv_bfloat16 g_qh [MROWS * D_MODEL];
__device__ __align__(16) __nv_bfloat16 g_ql [MROWS * D_MODEL];
__device__ __align__(16) __nv_bfloat16 g_kh [MROWS * D_MODEL];
__device__ __align__(16) __nv_bfloat16 g_kl [MROWS * D_MODEL];
__device__ __align__(16) __nv_bfloat16 g_vh [MROWS * D_MODEL];
__device__ __align__(16) __nv_bfloat16 g_vl [MROWS * D_MODEL];

// ---------------------------------------------------------------------------
// PTX helpers (sm_80-era, valid at compute_100)
// ---------------------------------------------------------------------------
__device__ __forceinline__ uint32_t smem_u32(const void* p) {
    uint32_t a;
    asm("{ .reg .u64 t; cvta.to.shared.u64 t, %1; cvt.u32.u64 %0, t; }"
        : "=r"(a) : "l"(p));
    return a;
}

__device__ __forceinline__ void cp_async16(uint32_t dst, const void* src) {
    asm volatile("cp.async.cg.shared.global [%0], [%1], 16;"
                 :: "r"(dst), "l"(src) : "memory");
}
#define CP_COMMIT() asm volatile("cp.async.commit_group;" ::: "memory")
#define CP_WAIT(n)  asm volatile("cp.async.wait_group %0;" :: "n"(n) : "memory")

#define LDSM4(r, addr) \
    asm volatile("ldmatrix.sync.aligned.m8n8.x4.shared.b16 {%0,%1,%2,%3}, [%4];" \
                 : "=r"((r)[0]), "=r"((r)[1]), "=r"((r)[2]), "=r"((r)[3]) : "r"(addr))

#define LDSM4T(r, addr) \
    asm volatile("ldmatrix.sync.aligned.m8n8.x4.trans.shared.b16 {%0,%1,%2,%3}, [%4];" \
                 : "=r"((r)[0]), "=r"((r)[1]), "=r"((r)[2]), "=r"((r)[3]) : "r"(addr))

#define MMA16816(d, a, b0v, b1v) \
    asm volatile("mma.sync.aligned.m16n8k16.row.col.f32.bf16.bf16.f32 " \
                 "{%0,%1,%2,%3}, {%4,%5,%6,%7}, {%8,%9}, {%0,%1,%2,%3};" \
                 : "+f"((d)[0]), "+f"((d)[1]), "+f"((d)[2]), "+f"((d)[3]) \
                 : "r"((a)[0]), "r"((a)[1]), "r"((a)[2]), "r"((a)[3]), \
                   "r"(b0v), "r"(b1v))

// pack two fp32 -> bf16x2 (lo = second operand)
__device__ __forceinline__ uint32_t bf2x(float hi, float lo) {
    uint32_t d;
    asm("cvt.rn.bf16x2.f32 %0, %1, %2;" : "=r"(d) : "f"(hi), "f"(lo));
    return d;
}
__device__ __forceinline__ float bf_round(float x) {
    return __bfloat162float(__float2bfloat16_rn(x));
}

// ---------------------------------------------------------------------------
// fp32 -> bf16 hi/lo split (with optional scale)
// ---------------------------------------------------------------------------
__global__ __launch_bounds__(256)
void split_bf16(const float* __restrict__ in, __nv_bfloat16* __restrict__ hi,
                __nv_bfloat16* __restrict__ lo, int n4, float scale)
{
    int i = blockIdx.x * blockDim.x + threadIdx.x;
    if (i >= n4) return;
    float4 v = ((const float4*)in)[i];
    float f[4] = {v.x * scale, v.y * scale, v.z * scale, v.w * scale};
    unsigned short hs[4], ls[4];
    #pragma unroll
    for (int j = 0; j < 4; j++) {
        __nv_bfloat16 h = __float2bfloat16_rn(f[j]);
        float r = f[j] - __bfloat162float(h);
        __nv_bfloat16 l = __float2bfloat16_rn(r);
        hs[j] = __bfloat16_as_ushort(h);
        ls[j] = __bfloat16_as_ushort(l);
    }
    ((ushort4*)hi)[i] = make_ushort4(hs[0], hs[1], hs[2], hs[3]);
    ((ushort4*)lo)[i] = make_ushort4(ls[0], ls[1], ls[2], ls[3]);
}

// ---------------------------------------------------------------------------
// bf16x3-split GEMM via mma.sync (unchanged, passing @ rel_err 1.45e-5)
// ---------------------------------------------------------------------------
#define TILE_B   10240
#define STAGE_B  (4 * TILE_B)
#define GSMEM    (2 * STAGE_B)
#define KT       (KDIM / 32)

__global__ __launch_bounds__(256, 1)
void gemm_bf16x3(const __nv_bfloat16* __restrict__ Agh,
                 const __nv_bfloat16* __restrict__ Agl,
                 const __nv_bfloat16* __restrict__ Bgh,
                 const __nv_bfloat16* __restrict__ Bgl,
                 float* __restrict__ C)
{
    extern __shared__ __align__(128) char smem_raw[];
    const uint32_t smem = smem_u32(smem_raw);

    const int tid    = threadIdx.x;
    const int lane   = tid & 31;
    const int wid    = tid >> 5;
    const int warp_m = wid & 1;
    const int warp_n = wid >> 1;
    const int row0   = blockIdx.y * 128;
    const int col0   = blockIdx.x * 128;

    const __nv_bfloat16* gsrc[4];
    gsrc[0] = Agh; gsrc[1] = Agl; gsrc[2] = Bgh; gsrc[3] = Bgl;
    int gbase[4];
    gbase[0] = row0; gbase[1] = row0; gbase[2] = col0; gbase[3] = col0;

    const uint32_t aoff = (uint32_t)((lane & 15) * 80 + ((lane >> 4) << 4));
    const uint32_t boff = (uint32_t)((((lane >> 3) & 1) * 8 + (lane & 7)) * 80 +
                                     ((lane >> 4) << 4));

    float acc[4][4][4];
    #pragma unroll
    for (int mt = 0; mt < 4; mt++)
        #pragma unroll
        for (int nt = 0; nt < 4; nt++)
            #pragma unroll
            for (int q = 0; q < 4; q++) acc[mt][nt][q] = 0.f;

    const int r_lo = tid >> 2;
    const int k16  = tid & 3;

    {
        const uint32_t sb = smem;
        #pragma unroll
        for (int i = 0; i < 8; i++) {
            const int tile = i >> 1;
            const int r    = ((i & 1) << 6) + r_lo;
            const __nv_bfloat16* gp =
                gsrc[tile] + (size_t)(gbase[tile] + r) * KDIM + k16 * 8;
            cp_async16(sb + tile * TILE_B + r * 80 + k16 * 16, gp);
        }
        CP_COMMIT();
    }

    for (int t = 0; t < KT; t++) {
        const int cur = t & 1;
        if (t + 1 < KT) {
            const uint32_t sb = smem + ((t + 1) & 1) * STAGE_B;
            const int k0 = (t + 1) * 32;
            #pragma unroll
            for (int i = 0; i < 8; i++) {
                const int tile = i >> 1;
                const int r    = ((i & 1) << 6) + r_lo;
                const __nv_bfloat16* gp =
                    gsrc[tile] + (size_t)(gbase[tile] + r) * KDIM + k0 + k16 * 8;
                cp_async16(sb + tile * TILE_B + r * 80 + k16 * 16, gp);
            }
            CP_COMMIT();
            CP_WAIT(1);
        } else {
            CP_WAIT(0);
        }
        __syncthreads();

        const uint32_t sb  = smem + cur * STAGE_B;
        const uint32_t Ahs = sb;
        const uint32_t Bhs = sb + 2 * TILE_B;

        #pragma unroll
        for (int kk = 0; kk < 2; kk++) {
            const uint32_t kkb = kk * 32;
            uint32_t ah[4][4];
            uint32_t al[4][4];
            uint32_t bh[2][4];
            uint32_t bl[2][4];
            #pragma unroll
            for (int mt = 0; mt < 4; mt++) {
                const uint32_t ad = Ahs + (warp_m * 64 + mt * 16) * 80 + kkb + aoff;
                LDSM4(ah[mt], ad);
                LDSM4(al[mt], ad + TILE_B);
            }
            #pragma unroll
            for (int p = 0; p < 2; p++) {
                const uint32_t bd = Bhs + (warp_n * 32 + p * 16) * 80 + kkb + boff;
                LDSM4(bh[p], bd);
                LDSM4(bl[p], bd + TILE_B);
            }
            #pragma unroll
            for (int mt = 0; mt < 4; mt++)
                #pragma unroll
                for (int nt = 0; nt < 4; nt++) {
                    float* d = acc[mt][nt];
                    const int p = nt >> 1;
                    const int q = nt & 1;
                    MMA16816(d, ah[mt], bh[p][q], bh[p][q + 2]);
                    MMA16816(d, ah[mt], bl[p][q], bl[p][q + 2]);
                    MMA16816(d, al[mt], bh[p][q], bh[p][q + 2]);
                }
        }
        __syncthreads();
    }

    const int rbase = row0 + warp_m * 64 + (lane >> 2);
    const int cbase = col0 + warp_n * 32 + (lane & 3) * 2;
    #pragma unroll
    for (int mt = 0; mt < 4; mt++) {
        #pragma unroll
        for (int nt = 0; nt < 4; nt++) {
            const int r = rbase + mt * 16;
            const int c = cbase + nt * 8;
            *(float2*)&C[(size_t)r * NDIM + c] =
                make_float2(acc[mt][nt][0], acc[mt][nt][1]);
            *(float2*)&C[(size_t)(r + 8) * NDIM + c] =
                make_float2(acc[mt][nt][2], acc[mt][nt][3]);
        }
    }
}

// ---------------------------------------------------------------------------
// Tensor-core causal flash attention, bf16x3 split.
// Grid (NQT, H, B), 256 threads (8 warps x 16 query rows = 128-row q-tile).
// K/V streamed in 64-key chunks, double-buffered cp.async.
// Q (pre-scaled) kept in registers as A-fragments. V via ldmatrix.trans.
// ---------------------------------------------------------------------------
#define APITCH  144                 // 64 bf16 = 128B data + 16B pad
#define KV_TILE (64 * APITCH)       // 9216
#define ASTAGE  (4 * KV_TILE)       // Kh Kl Vh Vl = 36864
#define ASMEM   (2 * ASTAGE)        // 73728

__global__ __launch_bounds__(256, 1)
void attn_mma(const __nv_bfloat16* __restrict__ Qh_, const __nv_bfloat16* __restrict__ Ql_,
              const __nv_bfloat16* __restrict__ Kh_, const __nv_bfloat16* __restrict__ Kl_,
              const __nv_bfloat16* __restrict__ Vh_, const __nv_bfloat16* __restrict__ Vl_,
              float* __restrict__ O)
{
    extern __shared__ __align__(128) char smx[];
    const uint32_t smem = smem_u32(smx);
    const int tid  = threadIdx.x;
    const int lane = tid & 31;
    const int w    = tid >> 5;
    const int qt   = (NQT - 1) - blockIdx.x;   // heavy tiles first
    const int h    = blockIdx.y;
    const int b    = blockIdx.z;
    const int q0   = qt * 128;
    const int hbase = h * 64;

    const uint32_t aoff = (uint32_t)((lane & 15) * APITCH + ((lane >> 4) << 4));
    const uint32_t boff = (uint32_t)((((lane >> 3) & 1) * 8 + (lane & 7)) * APITCH +
                                     ((lane >> 4) << 4));
    const uint32_t voff = aoff;   // same pattern for trans-ldsm on [key][dim]

    // ---- load Q hi/lo (128 x 64) into stage0 area, then to registers ----
    {
        const int r  = tid >> 1;               // 0..127
        const int c4 = (tid & 1) * 4;          // chunks c4..c4+3
        const size_t gq = ((size_t)(b * S_LEN + q0 + r)) * D_MODEL + hbase;
        const uint32_t d0 = smem + ((r >= 64) ? KV_TILE : 0) + (r & 63) * APITCH;
        #pragma unroll
        for (int j = 0; j < 4; j++) {
            cp_async16(d0 + (c4 + j) * 16, Qh_ + gq + (c4 + j) * 8);
            cp_async16(d0 + 2 * KV_TILE + (c4 + j) * 16, Ql_ + gq + (c4 + j) * 8);
        }
        CP_COMMIT();
        CP_WAIT(0);
    }
    __syncthreads();

    uint32_t qh[4][4], ql[4][4];
    {
        const uint32_t qtb = smem + ((w >= 4) ? KV_TILE : 0) + (w & 3) * 16 * APITCH;
        #pragma unroll
        for (int ks = 0; ks < 4; ks++) {
            LDSM4(qh[ks], qtb + ks * 32 + aoff);
            LDSM4(ql[ks], qtb + 2 * KV_TILE + ks * 32 + aoff);
        }
    }
    __syncthreads();   // Q consumed; stage0 free for K/V

    const __nv_bfloat16* kvsrc[4];
    kvsrc[0] = Kh_; kvsrc[1] = Kl_; kvsrc[2] = Vh_; kvsrc[3] = Vl_;

    float o[8][4];
    #pragma unroll
    for (int nt = 0; nt < 8; nt++)
        #pragma unroll
        for (int e = 0; e < 4; e++) o[nt][e] = 0.f;
    float mi0 = -1e30f, mi1 = -1e30f, li0 = 0.f, li1 = 0.f;

    const int nch = 2 * (qt + 1);
    const int r_lo = tid >> 3;                 // 0..31
    const int ch8  = tid & 7;

    // prologue: chunk 0
    {
        const uint32_t sb = smem;
        #pragma unroll
        for (int i = 0; i < 8; i++) {
            const int tile = i >> 1;
            const int r    = ((i & 1) << 5) + r_lo;
            const __nv_bfloat16* gp =
                kvsrc[tile] + ((size_t)(b * S_LEN + r)) * D_MODEL + hbase + ch8 * 8;
            cp_async16(sb + tile * KV_TILE + r * APITCH + ch8 * 16, gp);
        }
        CP_COMMIT();
    }

    for (int c = 0; c < nch; c++) {
        if (c + 1 < nch) {
            const uint32_t sb = smem + ((c + 1) & 1) * ASTAGE;
            const int k0 = (c + 1) * 64;
            #pragma unroll
            for (int i = 0; i < 8; i++) {
                const int tile = i >> 1;
                const int r    = ((i & 1) << 5) + r_lo;
                const __nv_bfloat16* gp =
                    kvsrc[tile] + ((size_t)(b * S_LEN + k0 + r)) * D_MODEL + hbase + ch8 * 8;
                cp_async16(sb + tile * KV_TILE + r * APITCH + ch8 * 16, gp);
            }
            CP_COMMIT();
            CP_WAIT(1);
        } else {
            CP_WAIT(0);
        }
        __syncthreads();

        const int c0 = c * 64;
        const uint32_t sb  = smem + (c & 1) * ASTAGE;
        const uint32_t Khs = sb;
        const uint32_t Kls = sb + KV_TILE;
        const uint32_t Vhs = sb + 2 * KV_TILE;
        const uint32_t Vls = sb + 3 * KV_TILE;

        // ---- scores: S = Q K^T ----
        float s[8][4];
        #pragma unroll
        for (int nt = 0; nt < 8; nt++)
            #pragma unroll
            for (int e = 0; e < 4; e++) s[nt][e] = 0.f;

        #pragma unroll
        for (int ks = 0; ks < 4; ks++) {
            uint32_t kh[4][4], kl[4][4];
            #pragma unroll
            for (int p = 0; p < 4; p++) {
                LDSM4(kh[p], Khs + p * 16 * APITCH + ks * 32 + boff);
                LDSM4(kl[p], Kls + p * 16 * APITCH + ks * 32 + boff);
            }
            #pragma unroll
            for (int nt = 0; nt < 8; nt++) {
                const int p = nt >> 1;
                const int q = nt & 1;
                MMA16816(s[nt], qh[ks], kh[p][q], kh[p][q + 2]);
                MMA16816(s[nt], ql[ks], kh[p][q], kh[p][q + 2]);
                MMA16816(s[nt], qh[ks], kl[p][q], kl[p][q + 2]);
            }
        }

        // ---- causal mask (only diagonal chunks) ----
        if (c0 >= q0) {
            const int qr0 = q0 + w * 16 + (lane >> 2);
            #pragma unroll
            for (int nt = 0; nt < 8; nt++)
                #pragma unroll
                for (int e = 0; e < 4; e++) {
                    const int key = c0 + nt * 8 + 2 * (lane & 3) + (e & 1);
                    const int qr  = qr0 + (e >> 1) * 8;
                    if (key > qr) s[nt][e] = -1e30f;
                }
        }

        // ---- online softmax (rows r0 = lane>>2 and r0+8) ----
        float rmax0 = -1e30f, rmax1 = -1e30f;
        #pragma unroll
        for (int nt = 0; nt < 8; nt++) {
            rmax0 = fmaxf(rmax0, fmaxf(s[nt][0], s[nt][1]));
            rmax1 = fmaxf(rmax1, fmaxf(s[nt][2], s[nt][3]));
        }
        rmax0 = fmaxf(rmax0, __shfl_xor_sync(0xffffffffu, rmax0, 1));
        rmax0 = fmaxf(rmax0, __shfl_xor_sync(0xffffffffu, rmax0, 2));
        rmax1 = fmaxf(rmax1, __shfl_xor_sync(0xffffffffu, rmax1, 1));
        rmax1 = fmaxf(rmax1, __shfl_xor_sync(0xffffffffu, rmax1, 2));

        const float mnew0 = fmaxf(mi0, rmax0);
        const float mnew1 = fmaxf(mi1, rmax1);
        const float alpha0 = __expf(mi0 - mnew0);
        const float alpha1 = __expf(mi1 - mnew1);
        mi0 = mnew0; mi1 = mnew1;

        float rsum0 = 0.f, rsum1 = 0.f;
        #pragma unroll
        for (int nt = 0; nt < 8; nt++) {
            s[nt][0] = __expf(s[nt][0] - mnew0);
            s[nt][1] = __expf(s[nt][1] - mnew0);
            s[nt][2] = __expf(s[nt][2] - mnew1);
            s[nt][3] = __expf(s[nt][3] - mnew1);
            rsum0 += s[nt][0] + s[nt][1];
            rsum1 += s[nt][2] + s[nt][3];
        }
        rsum0 += __shfl_xor_sync(0xffffffffu, rsum0, 1);
        rsum0 += __shfl_xor_sync(0xffffffffu, rsum0, 2);
        rsum1 += __shfl_xor_sync(0xffffffffu, rsum1, 1);
        rsum1 += __shfl_xor_sync(0xffffffffu, rsum1, 2);
        li0 = li0 * alpha0 + rsum0;
        li1 = li1 * alpha1 + rsum1;

        #pragma unroll
        for (int nt = 0; nt < 8; nt++) {
            o[nt][0] *= alpha0; o[nt][1] *= alpha0;
            o[nt][2] *= alpha1; o[nt][3] *= alpha1;
        }

        // ---- O += P V  (P split hi/lo in registers) ----
        #pragma unroll
        for (int kb = 0; kb < 4; kb++) {
            uint32_t ph[4], pl[4];
            {
                const float* s0 = s[2 * kb];
                const float* s1 = s[2 * kb + 1];
                float h00 = bf_round(s0[0]), h01 = bf_round(s0[1]);
                float h02 = bf_round(s0[2]), h03 = bf_round(s0[3]);
                float h10 = bf_round(s1[0]), h11 = bf_round(s1[1]);
                float h12 = bf_round(s1[2]), h13 = bf_round(s1[3]);
                ph[0] = bf2x(s0[1], s0[0]);
                ph[1] = bf2x(s0[3], s0[2]);
                ph[2] = bf2x(s1[1], s1[0]);
                ph[3] = bf2x(s1[3], s1[2]);
                pl[0] = bf2x(s0[1] - h01, s0[0] - h00);
                pl[1] = bf2x(s0[3] - h03, s0[2] - h02);
                pl[2] = bf2x(s1[1] - h11, s1[0] - h10);
                pl[3] = bf2x(s1[3] - h13, s1[2] - h12);
            }
            #pragma unroll
            for (int dt = 0; dt < 4; dt++) {
                uint32_t vh[4], vl[4];
                LDSM4T(vh, Vhs + kb * 16 * APITCH + dt * 32 + voff);
                LDSM4T(vl, Vls + kb * 16 * APITCH + dt * 32 + voff);
                #pragma unroll
                for (int q = 0; q < 2; q++) {
                    const int nt = dt * 2 + q;
                    MMA16816(o[nt], ph, vh[2 * q], vh[2 * q + 1]);
                    MMA16816(o[nt], pl, vh[2 * q], vh[2 * q + 1]);
                    MMA16816(o[nt], ph, vl[2 * q], vl[2 * q + 1]);
                }
            }
        }
        __syncthreads();
    }

    // ---- epilogue: normalize, write O[b][q][h*64+dim] ----
    const float inv0 = 1.f / li0;
    const float inv1 = 1.f / li1;
    const int qr0 = q0 + w * 16 + (lane >> 2);
    const int cb  = hbase + 2 * (lane & 3);
    #pragma unroll
    for (int nt = 0; nt < 8; nt++) {
        *(float2*)&O[((size_t)(b * S_LEN + qr0)) * D_MODEL + cb + nt * 8] =
            make_float2(o[nt][0] * inv0, o[nt][1] * inv0);
        *(float2*)&O[((size_t)(b * S_LEN + qr0 + 8)) * D_MODEL + cb + nt * 8] =
            make_float2(o[nt][2] * inv1, o[nt][3] * inv1);
    }
}

// ---------------------------------------------------------------------------
// Launch
// ---------------------------------------------------------------------------
extern "C" void kernel_launch(void* const* d_in, const int* in_sizes, int n_in,
                              void* d_out, int out_size)
{
    const float* x  = (const float*)d_in[0];
    float* out = (float*)d_out;

    float *pQ, *pK, *pV, *pAO;
    __nv_bfloat16 *pxh, *pxl, *paoh, *paol, *pwh, *pwl;
    __nv_bfloat16 *pqh, *pql, *pkh, *pkl, *pvh, *pvl;
    cudaGetSymbolAddress((void**)&pQ,   g_Q);
    cudaGetSymbolAddress((void**)&pK,   g_K);
    cudaGetSymbolAddress((void**)&pV,   g_V);
    cudaGetSymbolAddress((void**)&pAO,  g_AO);
    cudaGetSymbolAddress((void**)&pxh,  g_xh);
    cudaGetSymbolAddress((void**)&pxl,  g_xl);
    cudaGetSymbolAddress((void**)&paoh, g_aoh);
    cudaGetSymbolAddress((void**)&paol, g_aol);
    cudaGetSymbolAddress((void**)&pwh,  g_wh);
    cudaGetSymbolAddress((void**)&pwl,  g_wl);
    cudaGetSymbolAddress((void**)&pqh,  g_qh);
    cudaGetSymbolAddress((void**)&pql,  g_ql);
    cudaGetSymbolAddress((void**)&pkh,  g_kh);
    cudaGetSymbolAddress((void**)&pkl,  g_kl);
    cudaGetSymbolAddress((void**)&pvh,  g_vh);
    cudaGetSymbolAddress((void**)&pvl,  g_vl);

    cudaFuncSetAttribute(gemm_bf16x3,
                         cudaFuncAttributeMaxDynamicSharedMemorySize, GSMEM);
    cudaFuncSetAttribute(attn_mma,
                         cudaFuncAttributeMaxDynamicSharedMemorySize, ASMEM);

    const int n4e = MROWS * KDIM / 4;
    const int n4w = KDIM * NDIM / 4;

    // 1) split inputs
    split_bf16<<<(n4e + 255) / 256, 256>>>(x, pxh, pxl, n4e, 1.f);
    for (int w = 0; w < 4; w++)
        split_bf16<<<(n4w + 255) / 256, 256>>>(
            (const float*)d_in[1 + w],
            pwh + (size_t)w * KDIM * NDIM, pwl + (size_t)w * KDIM * NDIM,
            n4w, 1.f);

    // 2) Q/K/V projections
    dim3 ggrid(NDIM / 128, MROWS / 128);
    gemm_bf16x3<<<ggrid, 256, GSMEM>>>(pxh, pxl, pwh + 0 * (size_t)KDIM * NDIM,
                                       pwl + 0 * (size_t)KDIM * NDIM, pQ);
    gemm_bf16x3<<<ggrid, 256, GSMEM>>>(pxh, pxl, pwh + 1 * (size_t)KDIM * NDIM,
                                       pwl + 1 * (size_t)KDIM * NDIM, pK);
    gemm_bf16x3<<<ggrid, 256, GSMEM>>>(pxh, pxl, pwh + 2 * (size_t)KDIM * NDIM,
                                       pwl + 2 * (size_t)KDIM * NDIM, pV);

    // 3) split Q (scaled by 1/sqrt(dk)), K, V
    split_bf16<<<(n4e + 255) / 256, 256>>>(pQ, pqh, pql, n4e, 0.125f);
    split_bf16<<<(n4e + 255) / 256, 256>>>(pK, pkh, pkl, n4e, 1.f);
    split_bf16<<<(n4e + 255) / 256, 256>>>(pV, pvh, pvl, n4e, 1.f);

    // 4) tensor-core causal attention
    dim3 agrid(NQT, NHEAD, B_SZ);
    attn_mma<<<agrid, 256, ASMEM>>>(pqh, pql, pkh, pkl, pvh, pvl, pAO);

    // 5) output projection
    split_bf16<<<(n4e + 255) / 256, 256>>>(pAO, paoh, paol, n4e, 1.f);
    gemm_bf16x3<<<ggrid, 256, GSMEM>>>(paoh, paol, pwh + 3 * (size_t)KDIM * NDIM,
                                       pwl + 3 * (size_t)KDIM * NDIM, out);
}

// round 8
// speedup vs baseline: 2.6708x; 1.0655x over previous
#include <cuda_runtime.h>
#include <cuda_bf16.h>
#include <cstdint>
#include <math.h>

// ---------------------------------------------------------------------------
// Problem constants
// ---------------------------------------------------------------------------
#define B_SZ    2
#define S_LEN   2048
#define D_MODEL 1024
#define NHEAD   16
#define DKH     64
#define MROWS   4096
#define KDIM    1024
#define NDIM    1024
#define NQT     (S_LEN / 128)     // 16 q-tiles

// ---------------------------------------------------------------------------
// Scratch (device globals)
// ---------------------------------------------------------------------------
__device__ __align__(16) __nv_bfloat16 g_xh [MROWS * KDIM];
__device__ __align__(16) __nv_bfloat16 g_xl [MROWS * KDIM];
__device__ __align__(16) __nv_bfloat16 g_wh [4 * KDIM * NDIM];
__device__ __align__(16) __nv_bfloat16 g_wl [4 * KDIM * NDIM];
__device__ __align__(16) __nv_bfloat16 g_qh [MROWS * D_MODEL];
__device__ __align__(16) __nv_bfloat16 g_ql [MROWS * D_MODEL];
__device__ __align__(16) __nv_bfloat16 g_kh [MROWS * D_MODEL];
__device__ __align__(16) __nv_bfloat16 g_kl [MROWS * D_MODEL];
__device__ __align__(16) __nv_bfloat16 g_vh [MROWS * D_MODEL];
__device__ __align__(16) __nv_bfloat16 g_vl [MROWS * D_MODEL];
__device__ __align__(16) __nv_bfloat16 g_aoh[MROWS * D_MODEL];
__device__ __align__(16) __nv_bfloat16 g_aol[MROWS * D_MODEL];

// ---------------------------------------------------------------------------
// PTX helpers (sm_80-era, valid at compute_100)
// ---------------------------------------------------------------------------
__device__ __forceinline__ uint32_t smem_u32(const void* p) {
    uint32_t a;
    asm("{ .reg .u64 t; cvta.to.shared.u64 t, %1; cvt.u32.u64 %0, t; }"
        : "=r"(a) : "l"(p));
    return a;
}

__device__ __forceinline__ void cp_async16(uint32_t dst, const void* src) {
    asm volatile("cp.async.cg.shared.global [%0], [%1], 16;"
                 :: "r"(dst), "l"(src) : "memory");
}
#define CP_COMMIT() asm volatile("cp.async.commit_group;" ::: "memory")
#define CP_WAIT(n)  asm volatile("cp.async.wait_group %0;" :: "n"(n) : "memory")

#define LDSM4(r, addr) \
    asm volatile("ldmatrix.sync.aligned.m8n8.x4.shared.b16 {%0,%1,%2,%3}, [%4];" \
                 : "=r"((r)[0]), "=r"((r)[1]), "=r"((r)[2]), "=r"((r)[3]) : "r"(addr))

#define LDSM4T(r, addr) \
    asm volatile("ldmatrix.sync.aligned.m8n8.x4.trans.shared.b16 {%0,%1,%2,%3}, [%4];" \
                 : "=r"((r)[0]), "=r"((r)[1]), "=r"((r)[2]), "=r"((r)[3]) : "r"(addr))

#define MMA16816(d, a, b0v, b1v) \
    asm volatile("mma.sync.aligned.m16n8k16.row.col.f32.bf16.bf16.f32 " \
                 "{%0,%1,%2,%3}, {%4,%5,%6,%7}, {%8,%9}, {%0,%1,%2,%3};" \
                 : "+f"((d)[0]), "+f"((d)[1]), "+f"((d)[2]), "+f"((d)[3]) \
                 : "r"((a)[0]), "r"((a)[1]), "r"((a)[2]), "r"((a)[3]), \
                   "r"(b0v), "r"(b1v))

__device__ __forceinline__ uint32_t bf2x(float hi, float lo) {
    uint32_t d;
    asm("cvt.rn.bf16x2.f32 %0, %1, %2;" : "=r"(d) : "f"(hi), "f"(lo));
    return d;
}
__device__ __forceinline__ float bf_round(float x) {
    return __bfloat162float(__float2bfloat16_rn(x));
}

// ---------------------------------------------------------------------------
// fp32 -> bf16 hi/lo split (inputs only: x and the 4 weights)
// ---------------------------------------------------------------------------
__global__ __launch_bounds__(256)
void split_bf16(const float* __restrict__ in, __nv_bfloat16* __restrict__ hi,
                __nv_bfloat16* __restrict__ lo, int n4)
{
    int i = blockIdx.x * blockDim.x + threadIdx.x;
    if (i >= n4) return;
    float4 v = ((const float4*)in)[i];
    float f[4] = {v.x, v.y, v.z, v.w};
    unsigned short hs[4], ls[4];
    #pragma unroll
    for (int j = 0; j < 4; j++) {
        __nv_bfloat16 h = __float2bfloat16_rn(f[j]);
        float r = f[j] - __bfloat162float(h);
        __nv_bfloat16 l = __float2bfloat16_rn(r);
        hs[j] = __bfloat16_as_ushort(h);
        ls[j] = __bfloat16_as_ushort(l);
    }
    ((ushort4*)hi)[i] = make_ushort4(hs[0], hs[1], hs[2], hs[3]);
    ((ushort4*)lo)[i] = make_ushort4(ls[0], ls[1], ls[2], ls[3]);
}

// ---------------------------------------------------------------------------
// bf16x3-split GEMM via mma.sync:  C = A B^T (NT), 128x256x32 CTA tile.
// 256 threads, 8 warps (2m x 4n), warp tile 64x64, 4x8 m16n8k16 per warp.
// Epilogue: optional fp32 store (Cf) and/or fused bf16 hi/lo split store
// (Ch/Cl, values scaled by `scale` first).
// smem stage: Ah(10240) Al(10240) Bh(20480) Bl(20480) = 61440, x2 stages.
// ---------------------------------------------------------------------------
#define ATB     10240            // 128 * 80
#define BTB     20480            // 256 * 80
#define STG2    (2 * ATB + 2 * BTB)   // 61440
#define GSMEM2  (2 * STG2)            // 122880
#define KT      (KDIM / 32)           // 32

__global__ __launch_bounds__(256, 1)
void gemm_bf16x3(const __nv_bfloat16* __restrict__ Agh,
                 const __nv_bfloat16* __restrict__ Agl,
                 const __nv_bfloat16* __restrict__ Bgh,
                 const __nv_bfloat16* __restrict__ Bgl,
                 float* __restrict__ Cf,
                 __nv_bfloat16* __restrict__ Ch,
                 __nv_bfloat16* __restrict__ Cl,
                 float scale)
{
    extern __shared__ __align__(128) char smem_raw[];
    const uint32_t smem = smem_u32(smem_raw);

    const int tid    = threadIdx.x;
    const int lane   = tid & 31;
    const int wid    = tid >> 5;
    const int warp_m = wid & 1;        // 0..1 -> m offset 0/64
    const int warp_n = wid >> 1;       // 0..3 -> n offset 0/64/128/192
    const int row0   = blockIdx.y * 128;
    const int col0   = blockIdx.x * 256;

    const uint32_t aoff = (uint32_t)((lane & 15) * 80 + ((lane >> 4) << 4));
    const uint32_t boff = (uint32_t)((((lane >> 3) & 1) * 8 + (lane & 7)) * 80 +
                                     ((lane >> 4) << 4));

    float acc[4][8][4];
    #pragma unroll
    for (int mt = 0; mt < 4; mt++)
        #pragma unroll
        for (int nt = 0; nt < 8; nt++)
            #pragma unroll
            for (int q = 0; q < 4; q++) acc[mt][nt][q] = 0.f;

    const int r_lo = tid >> 2;          // 0..63
    const int k16  = tid & 3;           // 16B chunk of the 64B row payload

    // ---- stage loader: 12 x cp.async(16B)/thread ----
    // A(hi,lo): rows r_lo, r_lo+64.  B(hi,lo): rows r_lo + {0,64,128,192}.
    #define LOAD_STAGE(sb, k0)                                                  \
    do {                                                                        \
        const size_t kofs = (size_t)(k0) + k16 * 8;                             \
        _Pragma("unroll")                                                       \
        for (int rr = 0; rr < 2; rr++) {                                        \
            const int r = r_lo + rr * 64;                                       \
            cp_async16((sb) + r * 80 + k16 * 16,                                \
                       Agh + (size_t)(row0 + r) * KDIM + kofs);                 \
            cp_async16((sb) + ATB + r * 80 + k16 * 16,                          \
                       Agl + (size_t)(row0 + r) * KDIM + kofs);                 \
        }                                                                       \
        _Pragma("unroll")                                                       \
        for (int rr = 0; rr < 4; rr++) {                                        \
            const int r = r_lo + rr * 64;                                       \
            cp_async16((sb) + 2 * ATB + r * 80 + k16 * 16,                      \
                       Bgh + (size_t)(col0 + r) * KDIM + kofs);                 \
            cp_async16((sb) + 2 * ATB + BTB + r * 80 + k16 * 16,                \
                       Bgl + (size_t)(col0 + r) * KDIM + kofs);                 \
        }                                                                       \
    } while (0)

    LOAD_STAGE(smem, 0);
    CP_COMMIT();

    for (int t = 0; t < KT; t++) {
        const int cur = t & 1;
        if (t + 1 < KT) {
            const uint32_t sb = smem + ((t + 1) & 1) * STG2;
            LOAD_STAGE(sb, (t + 1) * 32);
            CP_COMMIT();
            CP_WAIT(1);
        } else {
            CP_WAIT(0);
        }
        __syncthreads();

        const uint32_t sb  = smem + cur * STG2;
        const uint32_t Ahs = sb;
        const uint32_t Bhs = sb + 2 * ATB;

        #pragma unroll
        for (int kk = 0; kk < 2; kk++) {
            const uint32_t kkb = kk * 32;
            uint32_t ah[4][4];
            uint32_t al[4][4];
            uint32_t bh[4][4];
            uint32_t bl[4][4];
            #pragma unroll
            for (int mt = 0; mt < 4; mt++) {
                const uint32_t ad = Ahs + (warp_m * 64 + mt * 16) * 80 + kkb + aoff;
                LDSM4(ah[mt], ad);
                LDSM4(al[mt], ad + ATB);
            }
            #pragma unroll
            for (int p = 0; p < 4; p++) {
                const uint32_t bd = Bhs + (warp_n * 64 + p * 16) * 80 + kkb + boff;
                LDSM4(bh[p], bd);
                LDSM4(bl[p], bd + BTB);
            }
            #pragma unroll
            for (int mt = 0; mt < 4; mt++)
                #pragma unroll
                for (int nt = 0; nt < 8; nt++) {
                    float* d = acc[mt][nt];
                    const int p = nt >> 1;
                    const int q = nt & 1;
                    MMA16816(d, ah[mt], bh[p][q], bh[p][q + 2]);
                    MMA16816(d, ah[mt], bl[p][q], bl[p][q + 2]);
                    MMA16816(d, al[mt], bh[p][q], bh[p][q + 2]);
                }
        }
        __syncthreads();
    }
    #undef LOAD_STAGE

    // ---- epilogue ----
    const int rbase = row0 + warp_m * 64 + (lane >> 2);
    const int cbase = col0 + warp_n * 64 + (lane & 3) * 2;
    #pragma unroll
    for (int mt = 0; mt < 4; mt++) {
        #pragma unroll
        for (int nt = 0; nt < 8; nt++) {
            const int r = rbase + mt * 16;
            const int c = cbase + nt * 8;
            const float v0 = acc[mt][nt][0] * scale;
            const float v1 = acc[mt][nt][1] * scale;
            const float v2 = acc[mt][nt][2] * scale;
            const float v3 = acc[mt][nt][3] * scale;
            if (Cf) {
                *(float2*)&Cf[(size_t)r * NDIM + c]       = make_float2(v0, v1);
                *(float2*)&Cf[(size_t)(r + 8) * NDIM + c] = make_float2(v2, v3);
            }
            if (Ch) {
                const float h0 = bf_round(v0), h1 = bf_round(v1);
                const float h2 = bf_round(v2), h3 = bf_round(v3);
                *(uint32_t*)&Ch[(size_t)r * NDIM + c]       = bf2x(v1, v0);
                *(uint32_t*)&Cl[(size_t)r * NDIM + c]       = bf2x(v1 - h1, v0 - h0);
                *(uint32_t*)&Ch[(size_t)(r + 8) * NDIM + c] = bf2x(v3, v2);
                *(uint32_t*)&Cl[(size_t)(r + 8) * NDIM + c] = bf2x(v3 - h3, v2 - h2);
            }
        }
    }
}

// ---------------------------------------------------------------------------
// Tensor-core causal flash attention, bf16x3 split (mainloop unchanged;
// epilogue now writes bf16 hi/lo directly).
// ---------------------------------------------------------------------------
#define APITCH  144
#define KV_TILE (64 * APITCH)
#define ASTAGE  (4 * KV_TILE)
#define ASMEM   (2 * ASTAGE)

__global__ __launch_bounds__(256, 1)
void attn_mma(const __nv_bfloat16* __restrict__ Qh_, const __nv_bfloat16* __restrict__ Ql_,
              const __nv_bfloat16* __restrict__ Kh_, const __nv_bfloat16* __restrict__ Kl_,
              const __nv_bfloat16* __restrict__ Vh_, const __nv_bfloat16* __restrict__ Vl_,
              __nv_bfloat16* __restrict__ AOh, __nv_bfloat16* __restrict__ AOl)
{
    extern __shared__ __align__(128) char smx[];
    const uint32_t smem = smem_u32(smx);
    const int tid  = threadIdx.x;
    const int lane = tid & 31;
    const int w    = tid >> 5;
    const int qt   = (NQT - 1) - blockIdx.x;
    const int h    = blockIdx.y;
    const int b    = blockIdx.z;
    const int q0   = qt * 128;
    const int hbase = h * 64;

    const uint32_t aoff = (uint32_t)((lane & 15) * APITCH + ((lane >> 4) << 4));
    const uint32_t boff = (uint32_t)((((lane >> 3) & 1) * 8 + (lane & 7)) * APITCH +
                                     ((lane >> 4) << 4));
    const uint32_t voff = aoff;

    // ---- load Q hi/lo (128 x 64) to smem, then A-fragments in registers ----
    {
        const int r  = tid >> 1;
        const int c4 = (tid & 1) * 4;
        const size_t gq = ((size_t)(b * S_LEN + q0 + r)) * D_MODEL + hbase;
        const uint32_t d0 = smem + ((r >= 64) ? KV_TILE : 0) + (r & 63) * APITCH;
        #pragma unroll
        for (int j = 0; j < 4; j++) {
            cp_async16(d0 + (c4 + j) * 16, Qh_ + gq + (c4 + j) * 8);
            cp_async16(d0 + 2 * KV_TILE + (c4 + j) * 16, Ql_ + gq + (c4 + j) * 8);
        }
        CP_COMMIT();
        CP_WAIT(0);
    }
    __syncthreads();

    uint32_t qh[4][4], ql[4][4];
    {
        const uint32_t qtb = smem + ((w >= 4) ? KV_TILE : 0) + (w & 3) * 16 * APITCH;
        #pragma unroll
        for (int ks = 0; ks < 4; ks++) {
            LDSM4(qh[ks], qtb + ks * 32 + aoff);
            LDSM4(ql[ks], qtb + 2 * KV_TILE + ks * 32 + aoff);
        }
    }
    __syncthreads();

    const __nv_bfloat16* kvsrc[4];
    kvsrc[0] = Kh_; kvsrc[1] = Kl_; kvsrc[2] = Vh_; kvsrc[3] = Vl_;

    float o[8][4];
    #pragma unroll
    for (int nt = 0; nt < 8; nt++)
        #pragma unroll
        for (int e = 0; e < 4; e++) o[nt][e] = 0.f;
    float mi0 = -1e30f, mi1 = -1e30f, li0 = 0.f, li1 = 0.f;

    const int nch = 2 * (qt + 1);
    const int r_lo = tid >> 3;
    const int ch8  = tid & 7;

    {
        const uint32_t sb = smem;
        #pragma unroll
        for (int i = 0; i < 8; i++) {
            const int tile = i >> 1;
            const int r    = ((i & 1) << 5) + r_lo;
            const __nv_bfloat16* gp =
                kvsrc[tile] + ((size_t)(b * S_LEN + r)) * D_MODEL + hbase + ch8 * 8;
            cp_async16(sb + tile * KV_TILE + r * APITCH + ch8 * 16, gp);
        }
        CP_COMMIT();
    }

    for (int c = 0; c < nch; c++) {
        if (c + 1 < nch) {
            const uint32_t sb = smem + ((c + 1) & 1) * ASTAGE;
            const int k0 = (c + 1) * 64;
            #pragma unroll
            for (int i = 0; i < 8; i++) {
                const int tile = i >> 1;
                const int r    = ((i & 1) << 5) + r_lo;
                const __nv_bfloat16* gp =
                    kvsrc[tile] + ((size_t)(b * S_LEN + k0 + r)) * D_MODEL + hbase + ch8 * 8;
                cp_async16(sb + tile * KV_TILE + r * APITCH + ch8 * 16, gp);
            }
            CP_COMMIT();
            CP_WAIT(1);
        } else {
            CP_WAIT(0);
        }
        __syncthreads();

        const int c0 = c * 64;
        const uint32_t sb  = smem + (c & 1) * ASTAGE;
        const uint32_t Khs = sb;
        const uint32_t Kls = sb + KV_TILE;
        const uint32_t Vhs = sb + 2 * KV_TILE;
        const uint32_t Vls = sb + 3 * KV_TILE;

        float s[8][4];
        #pragma unroll
        for (int nt = 0; nt < 8; nt++)
            #pragma unroll
            for (int e = 0; e < 4; e++) s[nt][e] = 0.f;

        #pragma unroll
        for (int ks = 0; ks < 4; ks++) {
            uint32_t kh[4][4], kl[4][4];
            #pragma unroll
            for (int p = 0; p < 4; p++) {
                LDSM4(kh[p], Khs + p * 16 * APITCH + ks * 32 + boff);
                LDSM4(kl[p], Kls + p * 16 * APITCH + ks * 32 + boff);
            }
            #pragma unroll
            for (int nt = 0; nt < 8; nt++) {
                const int p = nt >> 1;
                const int q = nt & 1;
                MMA16816(s[nt], qh[ks], kh[p][q], kh[p][q + 2]);
                MMA16816(s[nt], ql[ks], kh[p][q], kh[p][q + 2]);
                MMA16816(s[nt], qh[ks], kl[p][q], kl[p][q + 2]);
            }
        }

        if (c0 >= q0) {
            const int qr0 = q0 + w * 16 + (lane >> 2);
            #pragma unroll
            for (int nt = 0; nt < 8; nt++)
                #pragma unroll
                for (int e = 0; e < 4; e++) {
                    const int key = c0 + nt * 8 + 2 * (lane & 3) + (e & 1);
                    const int qr  = qr0 + (e >> 1) * 8;
                    if (key > qr) s[nt][e] = -1e30f;
                }
        }

        float rmax0 = -1e30f, rmax1 = -1e30f;
        #pragma unroll
        for (int nt = 0; nt < 8; nt++) {
            rmax0 = fmaxf(rmax0, fmaxf(s[nt][0], s[nt][1]));
            rmax1 = fmaxf(rmax1, fmaxf(s[nt][2], s[nt][3]));
        }
        rmax0 = fmaxf(rmax0, __shfl_xor_sync(0xffffffffu, rmax0, 1));
        rmax0 = fmaxf(rmax0, __shfl_xor_sync(0xffffffffu, rmax0, 2));
        rmax1 = fmaxf(rmax1, __shfl_xor_sync(0xffffffffu, rmax1, 1));
        rmax1 = fmaxf(rmax1, __shfl_xor_sync(0xffffffffu, rmax1, 2));

        const float mnew0 = fmaxf(mi0, rmax0);
        const float mnew1 = fmaxf(mi1, rmax1);
        const float alpha0 = __expf(mi0 - mnew0);
        const float alpha1 = __expf(mi1 - mnew1);
        mi0 = mnew0; mi1 = mnew1;

        float rsum0 = 0.f, rsum1 = 0.f;
        #pragma unroll
        for (int nt = 0; nt < 8; nt++) {
            s[nt][0] = __expf(s[nt][0] - mnew0);
            s[nt][1] = __expf(s[nt][1] - mnew0);
            s[nt][2] = __expf(s[nt][2] - mnew1);
            s[nt][3] = __expf(s[nt][3] - mnew1);
            rsum0 += s[nt][0] + s[nt][1];
            rsum1 += s[nt][2] + s[nt][3];
        }
        rsum0 += __shfl_xor_sync(0xffffffffu, rsum0, 1);
        rsum0 += __shfl_xor_sync(0xffffffffu, rsum0, 2);
        rsum1 += __shfl_xor_sync(0xffffffffu, rsum1, 1);
        rsum1 += __shfl_xor_sync(0xffffffffu, rsum1, 2);
        li0 = li0 * alpha0 + rsum0;
        li1 = li1 * alpha1 + rsum1;

        #pragma unroll
        for (int nt = 0; nt < 8; nt++) {
            o[nt][0] *= alpha0; o[nt][1] *= alpha0;
            o[nt][2] *= alpha1; o[nt][3] *= alpha1;
        }

        #pragma unroll
        for (int kb = 0; kb < 4; kb++) {
            uint32_t ph[4], pl[4];
            {
                const float* s0 = s[2 * kb];
                const float* s1 = s[2 * kb + 1];
                float h00 = bf_round(s0[0]), h01 = bf_round(s0[1]);
                float h02 = bf_round(s0[2]), h03 = bf_round(s0[3]);
                float h10 = bf_round(s1[0]), h11 = bf_round(s1[1]);
                float h12 = bf_round(s1[2]), h13 = bf_round(s1[3]);
                ph[0] = bf2x(s0[1], s0[0]);
                ph[1] = bf2x(s0[3], s0[2]);
                ph[2] = bf2x(s1[1], s1[0]);
                ph[3] = bf2x(s1[3], s1[2]);
                pl[0] = bf2x(s0[1] - h01, s0[0] - h00);
                pl[1] = bf2x(s0[3] - h03, s0[2] - h02);
                pl[2] = bf2x(s1[1] - h11, s1[0] - h10);
                pl[3] = bf2x(s1[3] - h13, s1[2] - h12);
            }
            #pragma unroll
            for (int dt = 0; dt < 4; dt++) {
                uint32_t vh[4], vl[4];
                LDSM4T(vh, Vhs + kb * 16 * APITCH + dt * 32 + voff);
                LDSM4T(vl, Vls + kb * 16 * APITCH + dt * 32 + voff);
                #pragma unroll
                for (int q = 0; q < 2; q++) {
                    const int nt = dt * 2 + q;
                    MMA16816(o[nt], ph, vh[2 * q], vh[2 * q + 1]);
                    MMA16816(o[nt], pl, vh[2 * q], vh[2 * q + 1]);
                    MMA16816(o[nt], ph, vl[2 * q], vl[2 * q + 1]);
                }
            }
        }
        __syncthreads();
    }

    // ---- epilogue: normalize, fused bf16 hi/lo split store ----
    const float inv0 = 1.f / li0;
    const float inv1 = 1.f / li1;
    const int qr0 = q0 + w * 16 + (lane >> 2);
    const int cb  = hbase + 2 * (lane & 3);
    #pragma unroll
    for (int nt = 0; nt < 8; nt++) {
        const float a0 = o[nt][0] * inv0, a1 = o[nt][1] * inv0;
        const float a2 = o[nt][2] * inv1, a3 = o[nt][3] * inv1;
        const float h0 = bf_round(a0), h1 = bf_round(a1);
        const float h2 = bf_round(a2), h3 = bf_round(a3);
        const size_t i0 = ((size_t)(b * S_LEN + qr0)) * D_MODEL + cb + nt * 8;
        const size_t i1 = ((size_t)(b * S_LEN + qr0 + 8)) * D_MODEL + cb + nt * 8;
        *(uint32_t*)&AOh[i0] = bf2x(a1, a0);
        *(uint32_t*)&AOl[i0] = bf2x(a1 - h1, a0 - h0);
        *(uint32_t*)&AOh[i1] = bf2x(a3, a2);
        *(uint32_t*)&AOl[i1] = bf2x(a3 - h3, a2 - h2);
    }
}

// ---------------------------------------------------------------------------
// Launch
// ---------------------------------------------------------------------------
extern "C" void kernel_launch(void* const* d_in, const int* in_sizes, int n_in,
                              void* d_out, int out_size)
{
    const float* x  = (const float*)d_in[0];
    float* out = (float*)d_out;

    __nv_bfloat16 *pxh, *pxl, *pwh, *pwl;
    __nv_bfloat16 *pqh, *pql, *pkh, *pkl, *pvh, *pvl, *paoh, *paol;
    cudaGetSymbolAddress((void**)&pxh,  g_xh);
    cudaGetSymbolAddress((void**)&pxl,  g_xl);
    cudaGetSymbolAddress((void**)&pwh,  g_wh);
    cudaGetSymbolAddress((void**)&pwl,  g_wl);
    cudaGetSymbolAddress((void**)&pqh,  g_qh);
    cudaGetSymbolAddress((void**)&pql,  g_ql);
    cudaGetSymbolAddress((void**)&pkh,  g_kh);
    cudaGetSymbolAddress((void**)&pkl,  g_kl);
    cudaGetSymbolAddress((void**)&pvh,  g_vh);
    cudaGetSymbolAddress((void**)&pvl,  g_vl);
    cudaGetSymbolAddress((void**)&paoh, g_aoh);
    cudaGetSymbolAddress((void**)&paol, g_aol);

    cudaFuncSetAttribute(gemm_bf16x3,
                         cudaFuncAttributeMaxDynamicSharedMemorySize, GSMEM2);
    cudaFuncSetAttribute(attn_mma,
                         cudaFuncAttributeMaxDynamicSharedMemorySize, ASMEM);

    const int n4e = MROWS * KDIM / 4;
    const int n4w = KDIM * NDIM / 4;

    // 1) split external inputs
    split_bf16<<<(n4e + 255) / 256, 256>>>(x, pxh, pxl, n4e);
    for (int w = 0; w < 4; w++)
        split_bf16<<<(n4w + 255) / 256, 256>>>(
            (const float*)d_in[1 + w],
            pwh + (size_t)w * KDIM * NDIM, pwl + (size_t)w * KDIM * NDIM, n4w);

    // 2) Q/K/V projections with fused hi/lo split epilogue (Q scaled 1/8)
    dim3 ggrid(NDIM / 256, MROWS / 128);   // (4, 32)
    gemm_bf16x3<<<ggrid, 256, GSMEM2>>>(pxh, pxl,
        pwh + 0 * (size_t)KDIM * NDIM, pwl + 0 * (size_t)KDIM * NDIM,
        (float*)nullptr, pqh, pql, 0.125f);
    gemm_bf16x3<<<ggrid, 256, GSMEM2>>>(pxh, pxl,
        pwh + 1 * (size_t)KDIM * NDIM, pwl + 1 * (size_t)KDIM * NDIM,
        (float*)nullptr, pkh, pkl, 1.f);
    gemm_bf16x3<<<ggrid, 256, GSMEM2>>>(pxh, pxl,
        pwh + 2 * (size_t)KDIM * NDIM, pwl + 2 * (size_t)KDIM * NDIM,
        (float*)nullptr, pvh, pvl, 1.f);

    // 3) tensor-core causal attention (writes aoh/aol directly)
    dim3 agrid(NQT, NHEAD, B_SZ);
    attn_mma<<<agrid, 256, ASMEM>>>(pqh, pql, pkh, pkl, pvh, pvl, paoh, paol);

    // 4) output projection -> fp32 out
    gemm_bf16x3<<<ggrid, 256, GSMEM2>>>(paoh, paol,
        pwh + 3 * (size_t)KDIM * NDIM, pwl + 3 * (size_t)KDIM * NDIM,
        out, (__nv_bfloat16*)nullptr, (__nv_bfloat16*)nullptr, 1.f);
}